// round 7
// baseline (speedup 1.0000x reference)
#include <cuda_runtime.h>
#include <cuda_fp16.h>
#include <cstdint>

// MoEGate hybrid, fp16x3 (Ootomo-style split) tensor fast path:
//   logits = X[T,2048] @ W[64,2048]^T ; fast path computes hi*hi + hi*lo + lo*hi
//   in f16 MMA with fp32 accumulate (operands pre-scaled by 2^4 / 2^6 so split
//   residuals stay normal in fp16; logits unscaled by 2^-10 exactly).
//   Epilogue: top-9; if any adjacent gap < EPS the ranking is ambiguous at fp32
//   noise level -> token goes to a per-CTA slot list; fixup kernel recomputes
//   those tokens with strict sequential-k fp32 (reference-matching, proven R1/R6).
// Output (float32): [T*8] topk weights, then [T*8] topk indices (as float).

#define H_DIM 2048
#define N_EXP 64
#define TOPK  8
#define BM    128
#define BN    64
#define BK    32
#define KTILES (H_DIM / BK)       // 64
#define NTHREADS 256
#define EPS   2e-4f
#define SCALE_X 16.0f
#define SCALE_W 64.0f
#define ISCALE  (1.0f / 1024.0f)

// smem stage layout (halfs, 64B rows, SW64 swizzle)
#define ST_XHI 0
#define ST_XLO 8192
#define ST_WHI 16384
#define ST_WLO 20480
#define STAGE_BYTES 24576
#define SMEM_BYTES (2 * STAGE_BYTES)   // 49152

__device__ int g_tok[128 * 128];       // per-CTA ambiguous-token slots (-1 = none)

static __device__ __forceinline__ uint32_t smem_u32(const void* p) {
    uint32_t a;
    asm("{ .reg .u64 t; cvta.to.shared.u64 t, %1; cvt.u32.u64 %0, t; }" : "=r"(a) : "l"(p));
    return a;
}
static __device__ __forceinline__ uint32_t swz64(uint32_t off) {   // SW64 (64B rows)
    return off ^ ((off >> 3) & 0x30);
}
static __device__ __forceinline__ void sts16(uint32_t addr, uint4 v) {
    asm volatile("st.shared.v4.b32 [%0], {%1,%2,%3,%4};"
                 :: "r"(addr), "r"(v.x), "r"(v.y), "r"(v.z), "r"(v.w) : "memory");
}
static __device__ __forceinline__ void ldsm4(uint32_t r[4], uint32_t addr) {
    asm volatile("ldmatrix.sync.aligned.m8n8.x4.shared.b16 {%0,%1,%2,%3}, [%4];"
                 : "=r"(r[0]), "=r"(r[1]), "=r"(r[2]), "=r"(r[3]) : "r"(addr));
}
static __device__ __forceinline__ uint32_t packh2(__half a, __half b) {
    return (uint32_t)__half_as_ushort(a) | ((uint32_t)__half_as_ushort(b) << 16);
}
// split 4 scaled floats into 4 hi halves (packed uint2) and 4 lo halves
static __device__ __forceinline__ void split4(float4 v, float s, uint2& h, uint2& l) {
    float x0 = v.x * s, x1 = v.y * s, x2 = v.z * s, x3 = v.w * s;
    __half h0 = __float2half_rn(x0), h1 = __float2half_rn(x1);
    __half h2 = __float2half_rn(x2), h3 = __float2half_rn(x3);
    __half l0 = __float2half_rn(x0 - __half2float(h0));
    __half l1 = __float2half_rn(x1 - __half2float(h1));
    __half l2 = __float2half_rn(x2 - __half2float(h2));
    __half l3 = __float2half_rn(x3 - __half2float(h3));
    h = make_uint2(packh2(h0, h1), packh2(h2, h3));
    l = make_uint2(packh2(l0, l1), packh2(l2, l3));
}
static __device__ __forceinline__ void mma16(float c[4], const uint32_t a[4],
                                             const uint32_t b[2]) {
    asm volatile(
        "mma.sync.aligned.m16n8k16.row.col.f32.f16.f16.f32 "
        "{%0,%1,%2,%3}, {%4,%5,%6,%7}, {%8,%9}, {%0,%1,%2,%3};"
        : "+f"(c[0]), "+f"(c[1]), "+f"(c[2]), "+f"(c[3])
        : "r"(a[0]), "r"(a[1]), "r"(a[2]), "r"(a[3]), "r"(b[0]), "r"(b[1]));
}

__global__ __launch_bounds__(NTHREADS, 1)
void moe_gate_fast(const float* __restrict__ X, const float* __restrict__ W,
                   float* __restrict__ out, int T) {
    extern __shared__ char smem_raw[];
    const uint32_t sbase = smem_u32(smem_raw);
    const int tid = threadIdx.x;
    const int block_m = blockIdx.x * BM;

    // ---- loader mapping ----
    const int xrow = tid >> 1, xk16 = (tid & 1) * 16;    // 16 floats per thread
    const int wrow = tid >> 2, wk8  = (tid & 3) * 8;     // 8 floats per thread
    const float* Xg = X + (size_t)(block_m + xrow) * H_DIM + xk16;
    const float* Wg = W + (size_t)wrow * H_DIM + wk8;
    const uint32_t xo1 = swz64((uint32_t)xrow * 64 + (uint32_t)xk16 * 2);
    const uint32_t xo2 = swz64((uint32_t)xrow * 64 + (uint32_t)xk16 * 2 + 16);
    const uint32_t wo  = swz64((uint32_t)wrow * 64 + (uint32_t)wk8 * 2);

    // ---- MMA mapping: 8 warps = 4(M) x 2(N), warp tile 32x32 ----
    const int wid = tid >> 5, lane = tid & 31;
    const int m0w = (wid & 3) * 32, n0w = (wid >> 2) * 32;
    const int gid = lane >> 2, tig = lane & 3;
    uint32_t a_base[2], b_base[2];
#pragma unroll
    for (int mt = 0; mt < 2; mt++)
        a_base[mt] = (uint32_t)(m0w + mt * 16 + (lane & 15)) * 64 + ((uint32_t)(lane >> 4) << 4);
#pragma unroll
    for (int p = 0; p < 2; p++)
        b_base[p] = (uint32_t)(n0w + p * 16 + (lane & 7) + ((lane >> 3) & 1) * 8) * 64 +
                    ((uint32_t)(lane >> 4) << 4);

    float acc[2][4][4];
#pragma unroll
    for (int mt = 0; mt < 2; mt++)
#pragma unroll
        for (int nf = 0; nf < 4; nf++)
#pragma unroll
            for (int r = 0; r < 4; r++) acc[mt][nf][r] = 0.f;

    float4 xreg[4], wreg[2];
    // prefetch tile 0
#pragma unroll
    for (int q = 0; q < 4; q++) xreg[q] = *reinterpret_cast<const float4*>(Xg + 4 * q);
    wreg[0] = *reinterpret_cast<const float4*>(Wg);
    wreg[1] = *reinterpret_cast<const float4*>(Wg + 4);

    for (int t = 0; t < KTILES; t++) {
        const uint32_t sb = sbase + (uint32_t)(t & 1) * STAGE_BYTES;

        // split + store current tile
        {
            uint2 h0, l0, h1, l1;
            split4(xreg[0], SCALE_X, h0, l0);
            split4(xreg[1], SCALE_X, h1, l1);
            sts16(sb + ST_XHI + xo1, make_uint4(h0.x, h0.y, h1.x, h1.y));
            sts16(sb + ST_XLO + xo1, make_uint4(l0.x, l0.y, l1.x, l1.y));
            split4(xreg[2], SCALE_X, h0, l0);
            split4(xreg[3], SCALE_X, h1, l1);
            sts16(sb + ST_XHI + xo2, make_uint4(h0.x, h0.y, h1.x, h1.y));
            sts16(sb + ST_XLO + xo2, make_uint4(l0.x, l0.y, l1.x, l1.y));
            split4(wreg[0], SCALE_W, h0, l0);
            split4(wreg[1], SCALE_W, h1, l1);
            sts16(sb + ST_WHI + wo, make_uint4(h0.x, h0.y, h1.x, h1.y));
            sts16(sb + ST_WLO + wo, make_uint4(l0.x, l0.y, l1.x, l1.y));
        }
        __syncthreads();

        // prefetch next tile (LDG in flight under compute)
        if (t + 1 < KTILES) {
            const float* xg = Xg + (t + 1) * BK;
            const float* wg = Wg + (t + 1) * BK;
#pragma unroll
            for (int q = 0; q < 4; q++) xreg[q] = *reinterpret_cast<const float4*>(xg + 4 * q);
            wreg[0] = *reinterpret_cast<const float4*>(wg);
            wreg[1] = *reinterpret_cast<const float4*>(wg + 4);
        }

        // compute: 2 k16 steps
#pragma unroll
        for (int s = 0; s < 2; s++) {
            const uint32_t ko = (uint32_t)s * 32;
            uint32_t ahi[2][4], alo[2][4], bhi[4][2], blo[4][2], r[4];
#pragma unroll
            for (int mt = 0; mt < 2; mt++) {
                ldsm4(ahi[mt], sb + ST_XHI + swz64(a_base[mt] + ko));
                ldsm4(alo[mt], sb + ST_XLO + swz64(a_base[mt] + ko));
            }
#pragma unroll
            for (int p = 0; p < 2; p++) {
                ldsm4(r, sb + ST_WHI + swz64(b_base[p] + ko));
                bhi[2 * p + 0][0] = r[0]; bhi[2 * p + 0][1] = r[2];
                bhi[2 * p + 1][0] = r[1]; bhi[2 * p + 1][1] = r[3];
                ldsm4(r, sb + ST_WLO + swz64(b_base[p] + ko));
                blo[2 * p + 0][0] = r[0]; blo[2 * p + 0][1] = r[2];
                blo[2 * p + 1][0] = r[1]; blo[2 * p + 1][1] = r[3];
            }
#pragma unroll
            for (int mt = 0; mt < 2; mt++)
#pragma unroll
                for (int nf = 0; nf < 4; nf++) {
                    mma16(acc[mt][nf], ahi[mt], bhi[nf]);   // hi*hi
                    mma16(acc[mt][nf], ahi[mt], blo[nf]);   // hi*lo
                    mma16(acc[mt][nf], alo[mt], bhi[nf]);   // lo*hi
                }
        }
        // double buffer: next store targets the other stage; barrier at t+1
        // orders every warp past compute(t) before any store to stage(t) at t+2.
    }

    __syncthreads();

    // logits[128][66] in smem (unscale by 2^-10)
    float* lg = reinterpret_cast<float*>(smem_raw);
#pragma unroll
    for (int mt = 0; mt < 2; mt++)
#pragma unroll
        for (int nf = 0; nf < 4; nf++) {
            const int col = n0w + nf * 8 + 2 * tig;
            const int row = m0w + mt * 16 + gid;
            *reinterpret_cast<float2*>(lg + row * 66 + col) =
                make_float2(acc[mt][nf][0] * ISCALE, acc[mt][nf][1] * ISCALE);
            *reinterpret_cast<float2*>(lg + (row + 8) * 66 + col) =
                make_float2(acc[mt][nf][2] * ISCALE, acc[mt][nf][3] * ISCALE);
        }
    __syncthreads();

    if (tid < BM) {
        float* row = lg + tid * 66;
        float vals[TOPK + 1];
        int   idxs[TOPK + 1];
#pragma unroll
        for (int r = 0; r < TOPK + 1; r++) {      // top-9 for gap check
            float best = -__int_as_float(0x7f800000);
            int bi = 0;
            for (int e = 0; e < N_EXP; e++) {
                float v = row[e];
                if (v > best) { best = v; bi = e; }
            }
            vals[r] = best;
            idxs[r] = bi;
            row[bi] = -__int_as_float(0x7f800000);
        }
        float mingap = vals[0] - vals[1];
#pragma unroll
        for (int r = 1; r < TOPK; r++) mingap = fminf(mingap, vals[r] - vals[r + 1]);

        const long long gtok = block_m + tid;
        // deterministic per-CTA slot list, rewritten fully every launch
        g_tok[blockIdx.x * BM + tid] = (mingap < EPS) ? (int)gtok : -1;

        const float m0f = vals[0];
        float wv[TOPK];
        float s = 0.f;
#pragma unroll
        for (int r = 0; r < TOPK; r++) { wv[r] = __expf(vals[r] - m0f); s += wv[r]; }
        const float inv = 1.f / s;
#pragma unroll
        for (int r = 0; r < TOPK; r++) {
            out[gtok * TOPK + r] = wv[r] * inv;
            out[(long long)T * TOPK + gtok * TOPK + r] = (float)idxs[r];
        }
    }
}

// exact slow path: strict sequential-k fp32 (order matches reference; proven R6)
__global__ __launch_bounds__(64, 8)
void moe_gate_fixup(const float* __restrict__ X, const float* __restrict__ W,
                    float* __restrict__ out, int T) {
    __shared__ float lg[N_EXP];
    const int e = threadIdx.x;              // 64 threads = 64 experts
    const int region = blockIdx.x >> 3;     // 128 regions (one per fast CTA)
    const int part = blockIdx.x & 7;

    for (int j = part; j < BM; j += 8) {
        const int tok = g_tok[region * BM + j];
        if (tok < 0) continue;              // uniform per block

        const float* x = X + (size_t)tok * H_DIM;
        const float* w = W + (size_t)e * H_DIM;
        float acc = 0.f;
#pragma unroll 4
        for (int k = 0; k < H_DIM; k += 4) {
            float4 xv = *reinterpret_cast<const float4*>(x + k);
            float4 wv = *reinterpret_cast<const float4*>(w + k);
            acc = fmaf(xv.x, wv.x, acc);    // strict sequential chain
            acc = fmaf(xv.y, wv.y, acc);
            acc = fmaf(xv.z, wv.z, acc);
            acc = fmaf(xv.w, wv.w, acc);
        }
        lg[e] = acc;
        __syncthreads();

        if (e == 0) {
            float vals[TOPK];
            int   idxs[TOPK];
#pragma unroll
            for (int r = 0; r < TOPK; r++) {
                float best = -__int_as_float(0x7f800000);
                int bi = 0;
                for (int q = 0; q < N_EXP; q++) {
                    float v = lg[q];
                    if (v > best) { best = v; bi = q; }
                }
                vals[r] = best;
                idxs[r] = bi;
                lg[bi] = -__int_as_float(0x7f800000);
            }
            const float m0f = vals[0];
            float wv[TOPK];
            float s = 0.f;
#pragma unroll
            for (int r = 0; r < TOPK; r++) { wv[r] = __expf(vals[r] - m0f); s += wv[r]; }
            const float inv = 1.f / s;
#pragma unroll
            for (int r = 0; r < TOPK; r++) {
                out[(long long)tok * TOPK + r] = wv[r] * inv;
                out[(long long)T * TOPK + (long long)tok * TOPK + r] = (float)idxs[r];
            }
        }
        __syncthreads();
    }
}

extern "C" void kernel_launch(void* const* d_in, const int* in_sizes, int n_in,
                              void* d_out, int out_size) {
    const float* X = (const float*)d_in[0];   // hidden_states [4,4096,2048] fp32
    const float* W = (const float*)d_in[1];   // weight [64,2048] fp32
    float* out = (float*)d_out;

    const int T = in_sizes[0] / H_DIM;        // 16384
    const int grid = T / BM;                  // 128

    cudaFuncSetAttribute(moe_gate_fast,
                         cudaFuncAttributeMaxDynamicSharedMemorySize, SMEM_BYTES);
    moe_gate_fast<<<grid, NTHREADS, SMEM_BYTES>>>(X, W, out, T);
    moe_gate_fixup<<<1024, 64>>>(X, W, out, T);
}

// round 8
// speedup vs baseline: 1.2630x; 1.2630x over previous
#include <cuda_runtime.h>
#include <cuda_fp16.h>
#include <cstdint>

// MoEGate hybrid, fp16x3 (Ootomo-style split) tensor fast path + exact fixup:
//   fast: logits = X @ W^T via f16 MMA computing hi*hi + hi*lo + lo*hi with fp32
//   accumulate (operands pre-scaled 2^4 / 2^6 so split residuals stay normal;
//   logits unscaled by 2^-10 exactly). top-9 gap check: ambiguous tokens
//   (adjacent gap < EPS) marked in a per-token slot array.
//   fixup: ONE BLOCK PER SLOT, recomputes marked tokens with strict
//   sequential-k fp32 (reference-matching, proven R1/R6); all ambiguous blocks
//   run their latency chains concurrently.
// Output (float32): [T*8] topk weights, then [T*8] topk indices (as float).

#define H_DIM 2048
#define N_EXP 64
#define TOPK  8
#define BM    128
#define BK    32
#define KTILES (H_DIM / BK)       // 64
#define NTHREADS 256
#define EPS   2e-4f
#define SCALE_X 16.0f
#define SCALE_W 64.0f
#define ISCALE  (1.0f / 1024.0f)

#define ST_XHI 0
#define ST_XLO 8192
#define ST_WHI 16384
#define ST_WLO 20480
#define STAGE_BYTES 24576
#define SMEM_BYTES (2 * STAGE_BYTES)   // 49152

__device__ int g_tok[16384];           // slot per token: token id or -1

static __device__ __forceinline__ uint32_t smem_u32(const void* p) {
    uint32_t a;
    asm("{ .reg .u64 t; cvta.to.shared.u64 t, %1; cvt.u32.u64 %0, t; }" : "=r"(a) : "l"(p));
    return a;
}
static __device__ __forceinline__ uint32_t swz64(uint32_t off) {   // SW64 (64B rows)
    return off ^ ((off >> 3) & 0x30);
}
static __device__ __forceinline__ void sts16(uint32_t addr, uint4 v) {
    asm volatile("st.shared.v4.b32 [%0], {%1,%2,%3,%4};"
                 :: "r"(addr), "r"(v.x), "r"(v.y), "r"(v.z), "r"(v.w) : "memory");
}
static __device__ __forceinline__ void ldsm4(uint32_t r[4], uint32_t addr) {
    asm volatile("ldmatrix.sync.aligned.m8n8.x4.shared.b16 {%0,%1,%2,%3}, [%4];"
                 : "=r"(r[0]), "=r"(r[1]), "=r"(r[2]), "=r"(r[3]) : "r"(addr));
}
static __device__ __forceinline__ uint32_t packh2(__half a, __half b) {
    return (uint32_t)__half_as_ushort(a) | ((uint32_t)__half_as_ushort(b) << 16);
}
static __device__ __forceinline__ void split4(float4 v, float s, uint2& h, uint2& l) {
    float x0 = v.x * s, x1 = v.y * s, x2 = v.z * s, x3 = v.w * s;
    __half h0 = __float2half_rn(x0), h1 = __float2half_rn(x1);
    __half h2 = __float2half_rn(x2), h3 = __float2half_rn(x3);
    __half l0 = __float2half_rn(x0 - __half2float(h0));
    __half l1 = __float2half_rn(x1 - __half2float(h1));
    __half l2 = __float2half_rn(x2 - __half2float(h2));
    __half l3 = __float2half_rn(x3 - __half2float(h3));
    h = make_uint2(packh2(h0, h1), packh2(h2, h3));
    l = make_uint2(packh2(l0, l1), packh2(l2, l3));
}
static __device__ __forceinline__ void mma16(float c[4], const uint32_t a[4],
                                             const uint32_t b[2]) {
    asm volatile(
        "mma.sync.aligned.m16n8k16.row.col.f32.f16.f16.f32 "
        "{%0,%1,%2,%3}, {%4,%5,%6,%7}, {%8,%9}, {%0,%1,%2,%3};"
        : "+f"(c[0]), "+f"(c[1]), "+f"(c[2]), "+f"(c[3])
        : "r"(a[0]), "r"(a[1]), "r"(a[2]), "r"(a[3]), "r"(b[0]), "r"(b[1]));
}

__global__ __launch_bounds__(NTHREADS, 1)
void moe_gate_fast(const float* __restrict__ X, const float* __restrict__ W,
                   float* __restrict__ out, int T) {
    extern __shared__ char smem_raw[];
    const uint32_t sbase = smem_u32(smem_raw);
    const int tid = threadIdx.x;
    const int block_m = blockIdx.x * BM;

    const int xrow = tid >> 1, xk16 = (tid & 1) * 16;
    const int wrow = tid >> 2, wk8  = (tid & 3) * 8;
    const float* Xg = X + (size_t)(block_m + xrow) * H_DIM + xk16;
    const float* Wg = W + (size_t)wrow * H_DIM + wk8;
    const uint32_t xo1 = swz64((uint32_t)xrow * 64 + (uint32_t)xk16 * 2);
    const uint32_t xo2 = swz64((uint32_t)xrow * 64 + (uint32_t)xk16 * 2 + 16);
    const uint32_t wo  = swz64((uint32_t)wrow * 64 + (uint32_t)wk8 * 2);

    const int wid = tid >> 5, lane = tid & 31;
    const int m0w = (wid & 3) * 32, n0w = (wid >> 2) * 32;
    const int gid = lane >> 2, tig = lane & 3;
    uint32_t a_base[2], b_base[2];
#pragma unroll
    for (int mt = 0; mt < 2; mt++)
        a_base[mt] = (uint32_t)(m0w + mt * 16 + (lane & 15)) * 64 + ((uint32_t)(lane >> 4) << 4);
#pragma unroll
    for (int p = 0; p < 2; p++)
        b_base[p] = (uint32_t)(n0w + p * 16 + (lane & 7) + ((lane >> 3) & 1) * 8) * 64 +
                    ((uint32_t)(lane >> 4) << 4);

    float acc[2][4][4];
#pragma unroll
    for (int mt = 0; mt < 2; mt++)
#pragma unroll
        for (int nf = 0; nf < 4; nf++)
#pragma unroll
            for (int r = 0; r < 4; r++) acc[mt][nf][r] = 0.f;

    float4 xreg[4], wreg[2];
#pragma unroll
    for (int q = 0; q < 4; q++) xreg[q] = *reinterpret_cast<const float4*>(Xg + 4 * q);
    wreg[0] = *reinterpret_cast<const float4*>(Wg);
    wreg[1] = *reinterpret_cast<const float4*>(Wg + 4);

    for (int t = 0; t < KTILES; t++) {
        const uint32_t sb = sbase + (uint32_t)(t & 1) * STAGE_BYTES;

        {
            uint2 h0, l0, h1, l1;
            split4(xreg[0], SCALE_X, h0, l0);
            split4(xreg[1], SCALE_X, h1, l1);
            sts16(sb + ST_XHI + xo1, make_uint4(h0.x, h0.y, h1.x, h1.y));
            sts16(sb + ST_XLO + xo1, make_uint4(l0.x, l0.y, l1.x, l1.y));
            split4(xreg[2], SCALE_X, h0, l0);
            split4(xreg[3], SCALE_X, h1, l1);
            sts16(sb + ST_XHI + xo2, make_uint4(h0.x, h0.y, h1.x, h1.y));
            sts16(sb + ST_XLO + xo2, make_uint4(l0.x, l0.y, l1.x, l1.y));
            split4(wreg[0], SCALE_W, h0, l0);
            split4(wreg[1], SCALE_W, h1, l1);
            sts16(sb + ST_WHI + wo, make_uint4(h0.x, h0.y, h1.x, h1.y));
            sts16(sb + ST_WLO + wo, make_uint4(l0.x, l0.y, l1.x, l1.y));
        }
        __syncthreads();

        if (t + 1 < KTILES) {
            const float* xg = Xg + (t + 1) * BK;
            const float* wg = Wg + (t + 1) * BK;
#pragma unroll
            for (int q = 0; q < 4; q++) xreg[q] = *reinterpret_cast<const float4*>(xg + 4 * q);
            wreg[0] = *reinterpret_cast<const float4*>(wg);
            wreg[1] = *reinterpret_cast<const float4*>(wg + 4);
        }

#pragma unroll
        for (int s = 0; s < 2; s++) {
            const uint32_t ko = (uint32_t)s * 32;
            uint32_t ahi[2][4], alo[2][4], bhi[4][2], blo[4][2], r[4];
#pragma unroll
            for (int mt = 0; mt < 2; mt++) {
                ldsm4(ahi[mt], sb + ST_XHI + swz64(a_base[mt] + ko));
                ldsm4(alo[mt], sb + ST_XLO + swz64(a_base[mt] + ko));
            }
#pragma unroll
            for (int p = 0; p < 2; p++) {
                ldsm4(r, sb + ST_WHI + swz64(b_base[p] + ko));
                bhi[2 * p + 0][0] = r[0]; bhi[2 * p + 0][1] = r[2];
                bhi[2 * p + 1][0] = r[1]; bhi[2 * p + 1][1] = r[3];
                ldsm4(r, sb + ST_WLO + swz64(b_base[p] + ko));
                blo[2 * p + 0][0] = r[0]; blo[2 * p + 0][1] = r[2];
                blo[2 * p + 1][0] = r[1]; blo[2 * p + 1][1] = r[3];
            }
#pragma unroll
            for (int mt = 0; mt < 2; mt++)
#pragma unroll
                for (int nf = 0; nf < 4; nf++) {
                    mma16(acc[mt][nf], ahi[mt], bhi[nf]);
                    mma16(acc[mt][nf], ahi[mt], blo[nf]);
                    mma16(acc[mt][nf], alo[mt], bhi[nf]);
                }
        }
    }

    __syncthreads();

    float* lg = reinterpret_cast<float*>(smem_raw);
#pragma unroll
    for (int mt = 0; mt < 2; mt++)
#pragma unroll
        for (int nf = 0; nf < 4; nf++) {
            const int col = n0w + nf * 8 + 2 * tig;
            const int row = m0w + mt * 16 + gid;
            *reinterpret_cast<float2*>(lg + row * 66 + col) =
                make_float2(acc[mt][nf][0] * ISCALE, acc[mt][nf][1] * ISCALE);
            *reinterpret_cast<float2*>(lg + (row + 8) * 66 + col) =
                make_float2(acc[mt][nf][2] * ISCALE, acc[mt][nf][3] * ISCALE);
        }
    __syncthreads();

    if (tid < BM) {
        float* row = lg + tid * 66;
        float vals[TOPK + 1];
        int   idxs[TOPK + 1];
#pragma unroll
        for (int r = 0; r < TOPK + 1; r++) {      // top-9 for gap check
            float best = -__int_as_float(0x7f800000);
            int bi = 0;
            for (int e = 0; e < N_EXP; e++) {
                float v = row[e];
                if (v > best) { best = v; bi = e; }
            }
            vals[r] = best;
            idxs[r] = bi;
            row[bi] = -__int_as_float(0x7f800000);
        }
        float mingap = vals[0] - vals[1];
#pragma unroll
        for (int r = 1; r < TOPK; r++) mingap = fminf(mingap, vals[r] - vals[r + 1]);

        const long long gtok = block_m + tid;
        g_tok[block_m + tid] = (mingap < EPS) ? (int)gtok : -1;   // deterministic

        const float m0f = vals[0];
        float wv[TOPK];
        float s = 0.f;
#pragma unroll
        for (int r = 0; r < TOPK; r++) { wv[r] = __expf(vals[r] - m0f); s += wv[r]; }
        const float inv = 1.f / s;
#pragma unroll
        for (int r = 0; r < TOPK; r++) {
            out[gtok * TOPK + r] = wv[r] * inv;
            out[(long long)T * TOPK + gtok * TOPK + r] = (float)idxs[r];
        }
    }
}

// exact slow path: one block per token slot; strict sequential-k fp32.
// All ambiguous blocks run their dependency chains concurrently.
__global__ __launch_bounds__(64, 16)
void moe_gate_fixup(const float* __restrict__ X, const float* __restrict__ W,
                    float* __restrict__ out, int T) {
    __shared__ float lg[N_EXP];
    const int tok = g_tok[blockIdx.x];
    if (tok < 0) return;                 // uniform: whole block exits

    const int e = threadIdx.x;           // 64 threads = 64 experts
    const float* x = X + (size_t)tok * H_DIM;
    const float* w = W + (size_t)e * H_DIM;
    float acc = 0.f;
#pragma unroll 8
    for (int k = 0; k < H_DIM; k += 4) {
        float4 xv = *reinterpret_cast<const float4*>(x + k);
        float4 wv = *reinterpret_cast<const float4*>(w + k);
        acc = fmaf(xv.x, wv.x, acc);     // strict sequential chain
        acc = fmaf(xv.y, wv.y, acc);
        acc = fmaf(xv.z, wv.z, acc);
        acc = fmaf(xv.w, wv.w, acc);
    }
    lg[e] = acc;
    __syncthreads();

    if (e == 0) {
        float vals[TOPK];
        int   idxs[TOPK];
#pragma unroll
        for (int r = 0; r < TOPK; r++) {
            float best = -__int_as_float(0x7f800000);
            int bi = 0;
            for (int q = 0; q < N_EXP; q++) {
                float v = lg[q];
                if (v > best) { best = v; bi = q; }
            }
            vals[r] = best;
            idxs[r] = bi;
            lg[bi] = -__int_as_float(0x7f800000);
        }
        const float m0f = vals[0];
        float wv[TOPK];
        float s = 0.f;
#pragma unroll
        for (int r = 0; r < TOPK; r++) { wv[r] = __expf(vals[r] - m0f); s += wv[r]; }
        const float inv = 1.f / s;
#pragma unroll
        for (int r = 0; r < TOPK; r++) {
            out[(long long)tok * TOPK + r] = wv[r] * inv;
            out[(long long)T * TOPK + (long long)tok * TOPK + r] = (float)idxs[r];
        }
    }
}

extern "C" void kernel_launch(void* const* d_in, const int* in_sizes, int n_in,
                              void* d_out, int out_size) {
    const float* X = (const float*)d_in[0];   // hidden_states [4,4096,2048] fp32
    const float* W = (const float*)d_in[1];   // weight [64,2048] fp32
    float* out = (float*)d_out;

    const int T = in_sizes[0] / H_DIM;        // 16384
    const int grid = T / BM;                  // 128

    cudaFuncSetAttribute(moe_gate_fast,
                         cudaFuncAttributeMaxDynamicSharedMemorySize, SMEM_BYTES);
    moe_gate_fast<<<grid, NTHREADS, SMEM_BYTES>>>(X, W, out, T);
    moe_gate_fixup<<<T, 64>>>(X, W, out, T);
}

// round 9
// speedup vs baseline: 1.4152x; 1.1205x over previous
#include <cuda_runtime.h>
#include <cuda_fp16.h>
#include <cstdint>

// MoEGate hybrid, fp16x3 (Ootomo-style split) tensor fast path + exact fixup:
//   fast: logits = X @ W^T via f16 MMA computing hi*hi + hi*lo + lo*hi with fp32
//   accumulate (operands pre-scaled 2^4 / 2^6; logits unscaled by 2^-10 exactly).
//   top-9 gap check marks ambiguous tokens (adjacent gap < EPS) in g_tok.
//   fixup: 2048 scan-blocks x 8 slots; each marked token recomputed with the
//   EXACT sequential-k fp32 chain (same order as R6/R8, reference-matching),
//   with X staged in smem and W software-pipelined to hide memory latency.
// Output (float32): [T*8] topk weights, then [T*8] topk indices (as float).

#define H_DIM 2048
#define N_EXP 64
#define TOPK  8
#define BM    128
#define BK    32
#define KTILES (H_DIM / BK)       // 64
#define NTHREADS 256
#define EPS   2e-4f
#define SCALE_X 16.0f
#define SCALE_W 64.0f
#define ISCALE  (1.0f / 1024.0f)

#define ST_XHI 0
#define ST_XLO 8192
#define ST_WHI 16384
#define ST_WLO 20480
#define STAGE_BYTES 24576
#define SMEM_BYTES (2 * STAGE_BYTES)   // 49152

#define FIX_BLOCKS 2048
#define FIX_SLOTS  8                   // 2048*8 = 16384 tokens

__device__ int g_tok[16384];           // slot per token: token id or -1

static __device__ __forceinline__ uint32_t smem_u32(const void* p) {
    uint32_t a;
    asm("{ .reg .u64 t; cvta.to.shared.u64 t, %1; cvt.u32.u64 %0, t; }" : "=r"(a) : "l"(p));
    return a;
}
static __device__ __forceinline__ uint32_t swz64(uint32_t off) {   // SW64 (64B rows)
    return off ^ ((off >> 3) & 0x30);
}
static __device__ __forceinline__ void sts16(uint32_t addr, uint4 v) {
    asm volatile("st.shared.v4.b32 [%0], {%1,%2,%3,%4};"
                 :: "r"(addr), "r"(v.x), "r"(v.y), "r"(v.z), "r"(v.w) : "memory");
}
static __device__ __forceinline__ void ldsm4(uint32_t r[4], uint32_t addr) {
    asm volatile("ldmatrix.sync.aligned.m8n8.x4.shared.b16 {%0,%1,%2,%3}, [%4];"
                 : "=r"(r[0]), "=r"(r[1]), "=r"(r[2]), "=r"(r[3]) : "r"(addr));
}
static __device__ __forceinline__ uint32_t packh2(__half a, __half b) {
    return (uint32_t)__half_as_ushort(a) | ((uint32_t)__half_as_ushort(b) << 16);
}
static __device__ __forceinline__ void split4(float4 v, float s, uint2& h, uint2& l) {
    float x0 = v.x * s, x1 = v.y * s, x2 = v.z * s, x3 = v.w * s;
    __half h0 = __float2half_rn(x0), h1 = __float2half_rn(x1);
    __half h2 = __float2half_rn(x2), h3 = __float2half_rn(x3);
    __half l0 = __float2half_rn(x0 - __half2float(h0));
    __half l1 = __float2half_rn(x1 - __half2float(h1));
    __half l2 = __float2half_rn(x2 - __half2float(h2));
    __half l3 = __float2half_rn(x3 - __half2float(h3));
    h = make_uint2(packh2(h0, h1), packh2(h2, h3));
    l = make_uint2(packh2(l0, l1), packh2(l2, l3));
}
static __device__ __forceinline__ void mma16(float c[4], const uint32_t a[4],
                                             const uint32_t b[2]) {
    asm volatile(
        "mma.sync.aligned.m16n8k16.row.col.f32.f16.f16.f32 "
        "{%0,%1,%2,%3}, {%4,%5,%6,%7}, {%8,%9}, {%0,%1,%2,%3};"
        : "+f"(c[0]), "+f"(c[1]), "+f"(c[2]), "+f"(c[3])
        : "r"(a[0]), "r"(a[1]), "r"(a[2]), "r"(a[3]), "r"(b[0]), "r"(b[1]));
}

__global__ __launch_bounds__(NTHREADS, 1)
void moe_gate_fast(const float* __restrict__ X, const float* __restrict__ W,
                   float* __restrict__ out, int T) {
    extern __shared__ char smem_raw[];
    const uint32_t sbase = smem_u32(smem_raw);
    const int tid = threadIdx.x;
    const int block_m = blockIdx.x * BM;

    const int xrow = tid >> 1, xk16 = (tid & 1) * 16;
    const int wrow = tid >> 2, wk8  = (tid & 3) * 8;
    const float* Xg = X + (size_t)(block_m + xrow) * H_DIM + xk16;
    const float* Wg = W + (size_t)wrow * H_DIM + wk8;
    const uint32_t xo1 = swz64((uint32_t)xrow * 64 + (uint32_t)xk16 * 2);
    const uint32_t xo2 = swz64((uint32_t)xrow * 64 + (uint32_t)xk16 * 2 + 16);
    const uint32_t wo  = swz64((uint32_t)wrow * 64 + (uint32_t)wk8 * 2);

    const int wid = tid >> 5, lane = tid & 31;
    const int m0w = (wid & 3) * 32, n0w = (wid >> 2) * 32;
    const int gid = lane >> 2, tig = lane & 3;
    uint32_t a_base[2], b_base[2];
#pragma unroll
    for (int mt = 0; mt < 2; mt++)
        a_base[mt] = (uint32_t)(m0w + mt * 16 + (lane & 15)) * 64 + ((uint32_t)(lane >> 4) << 4);
#pragma unroll
    for (int p = 0; p < 2; p++)
        b_base[p] = (uint32_t)(n0w + p * 16 + (lane & 7) + ((lane >> 3) & 1) * 8) * 64 +
                    ((uint32_t)(lane >> 4) << 4);

    float acc[2][4][4];
#pragma unroll
    for (int mt = 0; mt < 2; mt++)
#pragma unroll
        for (int nf = 0; nf < 4; nf++)
#pragma unroll
            for (int r = 0; r < 4; r++) acc[mt][nf][r] = 0.f;

    float4 xreg[4], wreg[2];
#pragma unroll
    for (int q = 0; q < 4; q++) xreg[q] = *reinterpret_cast<const float4*>(Xg + 4 * q);
    wreg[0] = *reinterpret_cast<const float4*>(Wg);
    wreg[1] = *reinterpret_cast<const float4*>(Wg + 4);

    for (int t = 0; t < KTILES; t++) {
        const uint32_t sb = sbase + (uint32_t)(t & 1) * STAGE_BYTES;

        {
            uint2 h0, l0, h1, l1;
            split4(xreg[0], SCALE_X, h0, l0);
            split4(xreg[1], SCALE_X, h1, l1);
            sts16(sb + ST_XHI + xo1, make_uint4(h0.x, h0.y, h1.x, h1.y));
            sts16(sb + ST_XLO + xo1, make_uint4(l0.x, l0.y, l1.x, l1.y));
            split4(xreg[2], SCALE_X, h0, l0);
            split4(xreg[3], SCALE_X, h1, l1);
            sts16(sb + ST_XHI + xo2, make_uint4(h0.x, h0.y, h1.x, h1.y));
            sts16(sb + ST_XLO + xo2, make_uint4(l0.x, l0.y, l1.x, l1.y));
            split4(wreg[0], SCALE_W, h0, l0);
            split4(wreg[1], SCALE_W, h1, l1);
            sts16(sb + ST_WHI + wo, make_uint4(h0.x, h0.y, h1.x, h1.y));
            sts16(sb + ST_WLO + wo, make_uint4(l0.x, l0.y, l1.x, l1.y));
        }
        __syncthreads();

        if (t + 1 < KTILES) {
            const float* xg = Xg + (t + 1) * BK;
            const float* wg = Wg + (t + 1) * BK;
#pragma unroll
            for (int q = 0; q < 4; q++) xreg[q] = *reinterpret_cast<const float4*>(xg + 4 * q);
            wreg[0] = *reinterpret_cast<const float4*>(wg);
            wreg[1] = *reinterpret_cast<const float4*>(wg + 4);
        }

#pragma unroll
        for (int s = 0; s < 2; s++) {
            const uint32_t ko = (uint32_t)s * 32;
            uint32_t ahi[2][4], alo[2][4], bhi[4][2], blo[4][2], r[4];
#pragma unroll
            for (int mt = 0; mt < 2; mt++) {
                ldsm4(ahi[mt], sb + ST_XHI + swz64(a_base[mt] + ko));
                ldsm4(alo[mt], sb + ST_XLO + swz64(a_base[mt] + ko));
            }
#pragma unroll
            for (int p = 0; p < 2; p++) {
                ldsm4(r, sb + ST_WHI + swz64(b_base[p] + ko));
                bhi[2 * p + 0][0] = r[0]; bhi[2 * p + 0][1] = r[2];
                bhi[2 * p + 1][0] = r[1]; bhi[2 * p + 1][1] = r[3];
                ldsm4(r, sb + ST_WLO + swz64(b_base[p] + ko));
                blo[2 * p + 0][0] = r[0]; blo[2 * p + 0][1] = r[2];
                blo[2 * p + 1][0] = r[1]; blo[2 * p + 1][1] = r[3];
            }
#pragma unroll
            for (int mt = 0; mt < 2; mt++)
#pragma unroll
                for (int nf = 0; nf < 4; nf++) {
                    mma16(acc[mt][nf], ahi[mt], bhi[nf]);
                    mma16(acc[mt][nf], ahi[mt], blo[nf]);
                    mma16(acc[mt][nf], alo[mt], bhi[nf]);
                }
        }
    }

    __syncthreads();

    float* lg = reinterpret_cast<float*>(smem_raw);
#pragma unroll
    for (int mt = 0; mt < 2; mt++)
#pragma unroll
        for (int nf = 0; nf < 4; nf++) {
            const int col = n0w + nf * 8 + 2 * tig;
            const int row = m0w + mt * 16 + gid;
            *reinterpret_cast<float2*>(lg + row * 66 + col) =
                make_float2(acc[mt][nf][0] * ISCALE, acc[mt][nf][1] * ISCALE);
            *reinterpret_cast<float2*>(lg + (row + 8) * 66 + col) =
                make_float2(acc[mt][nf][2] * ISCALE, acc[mt][nf][3] * ISCALE);
        }
    __syncthreads();

    if (tid < BM) {
        float* row = lg + tid * 66;
        float vals[TOPK + 1];
        int   idxs[TOPK + 1];
#pragma unroll
        for (int r = 0; r < TOPK + 1; r++) {      // top-9 for gap check
            float best = -__int_as_float(0x7f800000);
            int bi = 0;
            for (int e = 0; e < N_EXP; e++) {
                float v = row[e];
                if (v > best) { best = v; bi = e; }
            }
            vals[r] = best;
            idxs[r] = bi;
            row[bi] = -__int_as_float(0x7f800000);
        }
        float mingap = vals[0] - vals[1];
#pragma unroll
        for (int r = 1; r < TOPK; r++) mingap = fminf(mingap, vals[r] - vals[r + 1]);

        const long long gtok = block_m + tid;
        g_tok[block_m + tid] = (mingap < EPS) ? (int)gtok : -1;   // deterministic

        const float m0f = vals[0];
        float wv[TOPK];
        float s = 0.f;
#pragma unroll
        for (int r = 0; r < TOPK; r++) { wv[r] = __expf(vals[r] - m0f); s += wv[r]; }
        const float inv = 1.f / s;
#pragma unroll
        for (int r = 0; r < TOPK; r++) {
            out[gtok * TOPK + r] = wv[r] * inv;
            out[(long long)T * TOPK + gtok * TOPK + r] = (float)idxs[r];
        }
    }
}

// exact slow path: 2048 scan-blocks x 8 strided slots. For each marked token:
// X row staged in smem (kills DRAM latency in chain), W software-pipelined in
// 64-k register chunks (L2 latency covered by the 256-cyc chain per chunk).
// The fmaf accumulation ORDER is identical to R6/R8 (k ascending, xyzw).
__global__ __launch_bounds__(64, 4)
void moe_gate_fixup(const float* __restrict__ X, const float* __restrict__ W,
                    float* __restrict__ out, int T) {
    __shared__ float xs[H_DIM];          // 8 KB staged X row
    __shared__ float lg[N_EXP];
    const int e = threadIdx.x;           // 64 threads = 64 experts
    const float* w = W + (size_t)e * H_DIM;

    for (int s = 0; s < FIX_SLOTS; s++) {
        const int tok = g_tok[blockIdx.x + s * FIX_BLOCKS];
        if (tok < 0) continue;           // uniform: all threads agree

        __syncthreads();                 // protect xs/lg from previous iteration
        {
            const float4* xg = reinterpret_cast<const float4*>(X + (size_t)tok * H_DIM);
            float4* xd = reinterpret_cast<float4*>(xs);
#pragma unroll
            for (int i = 0; i < H_DIM / 4 / 64; i++) xd[e + i * 64] = xg[e + i * 64];
        }
        __syncthreads();

        float acc = 0.f;
        float4 bufA[16], bufB[16];
        const float4* w4 = reinterpret_cast<const float4*>(w);
#pragma unroll
        for (int j = 0; j < 16; j++) bufA[j] = w4[j];

        for (int c = 0; c < 32; c += 2) {      // 64-k chunks, ping-pong prefetch
            if (c + 1 < 32) {
#pragma unroll
                for (int j = 0; j < 16; j++) bufB[j] = w4[(c + 1) * 16 + j];
            }
            const float4* xc = reinterpret_cast<const float4*>(xs + c * 64);
#pragma unroll
            for (int j = 0; j < 16; j++) {     // strict sequential chain
                float4 xv = xc[j];
                acc = fmaf(xv.x, bufA[j].x, acc);
                acc = fmaf(xv.y, bufA[j].y, acc);
                acc = fmaf(xv.z, bufA[j].z, acc);
                acc = fmaf(xv.w, bufA[j].w, acc);
            }
            if (c + 2 < 32) {
#pragma unroll
                for (int j = 0; j < 16; j++) bufA[j] = w4[(c + 2) * 16 + j];
            }
            const float4* xc2 = reinterpret_cast<const float4*>(xs + (c + 1) * 64);
#pragma unroll
            for (int j = 0; j < 16; j++) {
                float4 xv = xc2[j];
                acc = fmaf(xv.x, bufB[j].x, acc);
                acc = fmaf(xv.y, bufB[j].y, acc);
                acc = fmaf(xv.z, bufB[j].z, acc);
                acc = fmaf(xv.w, bufB[j].w, acc);
            }
        }
        lg[e] = acc;
        __syncthreads();

        if (e == 0) {
            float vals[TOPK];
            int   idxs[TOPK];
#pragma unroll
            for (int r = 0; r < TOPK; r++) {
                float best = -__int_as_float(0x7f800000);
                int bi = 0;
                for (int q = 0; q < N_EXP; q++) {
                    float v = lg[q];
                    if (v > best) { best = v; bi = q; }
                }
                vals[r] = best;
                idxs[r] = bi;
                lg[bi] = -__int_as_float(0x7f800000);
            }
            const float m0f = vals[0];
            float wv[TOPK];
            float sm = 0.f;
#pragma unroll
            for (int r = 0; r < TOPK; r++) { wv[r] = __expf(vals[r] - m0f); sm += wv[r]; }
            const float inv = 1.f / sm;
#pragma unroll
            for (int r = 0; r < TOPK; r++) {
                out[(long long)tok * TOPK + r] = wv[r] * inv;
                out[(long long)T * TOPK + (long long)tok * TOPK + r] = (float)idxs[r];
            }
        }
    }
}

extern "C" void kernel_launch(void* const* d_in, const int* in_sizes, int n_in,
                              void* d_out, int out_size) {
    const float* X = (const float*)d_in[0];   // hidden_states [4,4096,2048] fp32
    const float* W = (const float*)d_in[1];   // weight [64,2048] fp32
    float* out = (float*)d_out;

    const int T = in_sizes[0] / H_DIM;        // 16384
    const int grid = T / BM;                  // 128

    cudaFuncSetAttribute(moe_gate_fast,
                         cudaFuncAttributeMaxDynamicSharedMemorySize, SMEM_BYTES);
    moe_gate_fast<<<grid, NTHREADS, SMEM_BYTES>>>(X, W, out, T);
    moe_gate_fixup<<<FIX_BLOCKS, 64>>>(X, W, out, T);
}

// round 10
// speedup vs baseline: 1.9544x; 1.3810x over previous
#include <cuda_runtime.h>
#include <cuda_fp16.h>
#include <cstdint>

// MoEGate hybrid, fp16x3 (Ootomo-style split) tensor fast path + exact fixup:
//   fast: logits = X @ W^T via f16 MMA computing hi*hi + hi*lo + lo*hi with fp32
//   accumulate (operands pre-scaled 2^4 / 2^6; logits unscaled by 2^-10 exactly).
//   top-9 gap check marks ambiguous tokens (adjacent gap < EPS) in g_tok.
//   compact: dense list of marked tokens (list order irrelevant to output).
//   fixup: ONE BLOCK PER DENSE TOKEN -> all exact sequential-k fp32 chains
//   (reference-matching order, proven R6/R8/R9) run in a single chain-wave.
// Output (float32): [T*8] topk weights, then [T*8] topk indices (as float).

#define H_DIM 2048
#define N_EXP 64
#define TOPK  8
#define BM    128
#define BK    32
#define KTILES (H_DIM / BK)       // 64
#define NTHREADS 256
#define EPS   2e-4f
#define SCALE_X 16.0f
#define SCALE_W 64.0f
#define ISCALE  (1.0f / 1024.0f)

#define ST_XHI 0
#define ST_XLO 8192
#define ST_WHI 16384
#define ST_WLO 20480
#define STAGE_BYTES 24576
#define SMEM_BYTES (2 * STAGE_BYTES)   // 49152

#define FIX_GRID 2048                  // upper bound on ambiguous tokens

__device__ int g_tok[16384];           // per-token flag: token id or -1
__device__ int g_list[FIX_GRID];       // compacted ambiguous tokens
__device__ int g_cnt;                  // compacted count

static __device__ __forceinline__ uint32_t smem_u32(const void* p) {
    uint32_t a;
    asm("{ .reg .u64 t; cvta.to.shared.u64 t, %1; cvt.u32.u64 %0, t; }" : "=r"(a) : "l"(p));
    return a;
}
static __device__ __forceinline__ uint32_t swz64(uint32_t off) {   // SW64 (64B rows)
    return off ^ ((off >> 3) & 0x30);
}
static __device__ __forceinline__ void sts16(uint32_t addr, uint4 v) {
    asm volatile("st.shared.v4.b32 [%0], {%1,%2,%3,%4};"
                 :: "r"(addr), "r"(v.x), "r"(v.y), "r"(v.z), "r"(v.w) : "memory");
}
static __device__ __forceinline__ void ldsm4(uint32_t r[4], uint32_t addr) {
    asm volatile("ldmatrix.sync.aligned.m8n8.x4.shared.b16 {%0,%1,%2,%3}, [%4];"
                 : "=r"(r[0]), "=r"(r[1]), "=r"(r[2]), "=r"(r[3]) : "r"(addr));
}
static __device__ __forceinline__ uint32_t packh2(__half a, __half b) {
    return (uint32_t)__half_as_ushort(a) | ((uint32_t)__half_as_ushort(b) << 16);
}
static __device__ __forceinline__ void split4(float4 v, float s, uint2& h, uint2& l) {
    float x0 = v.x * s, x1 = v.y * s, x2 = v.z * s, x3 = v.w * s;
    __half h0 = __float2half_rn(x0), h1 = __float2half_rn(x1);
    __half h2 = __float2half_rn(x2), h3 = __float2half_rn(x3);
    __half l0 = __float2half_rn(x0 - __half2float(h0));
    __half l1 = __float2half_rn(x1 - __half2float(h1));
    __half l2 = __float2half_rn(x2 - __half2float(h2));
    __half l3 = __float2half_rn(x3 - __half2float(h3));
    h = make_uint2(packh2(h0, h1), packh2(h2, h3));
    l = make_uint2(packh2(l0, l1), packh2(l2, l3));
}
static __device__ __forceinline__ void mma16(float c[4], const uint32_t a[4],
                                             const uint32_t b[2]) {
    asm volatile(
        "mma.sync.aligned.m16n8k16.row.col.f32.f16.f16.f32 "
        "{%0,%1,%2,%3}, {%4,%5,%6,%7}, {%8,%9}, {%0,%1,%2,%3};"
        : "+f"(c[0]), "+f"(c[1]), "+f"(c[2]), "+f"(c[3])
        : "r"(a[0]), "r"(a[1]), "r"(a[2]), "r"(a[3]), "r"(b[0]), "r"(b[1]));
}

__global__ __launch_bounds__(NTHREADS, 1)
void moe_gate_fast(const float* __restrict__ X, const float* __restrict__ W,
                   float* __restrict__ out, int T) {
    extern __shared__ char smem_raw[];
    const uint32_t sbase = smem_u32(smem_raw);
    const int tid = threadIdx.x;
    const int block_m = blockIdx.x * BM;

    // counter reset for the compact kernel (kernel-boundary orders this
    // before any compact-kernel read; deterministic).
    if (blockIdx.x == 0 && tid == 0) g_cnt = 0;

    const int xrow = tid >> 1, xk16 = (tid & 1) * 16;
    const int wrow = tid >> 2, wk8  = (tid & 3) * 8;
    const float* Xg = X + (size_t)(block_m + xrow) * H_DIM + xk16;
    const float* Wg = W + (size_t)wrow * H_DIM + wk8;
    const uint32_t xo1 = swz64((uint32_t)xrow * 64 + (uint32_t)xk16 * 2);
    const uint32_t xo2 = swz64((uint32_t)xrow * 64 + (uint32_t)xk16 * 2 + 16);
    const uint32_t wo  = swz64((uint32_t)wrow * 64 + (uint32_t)wk8 * 2);

    const int wid = tid >> 5, lane = tid & 31;
    const int m0w = (wid & 3) * 32, n0w = (wid >> 2) * 32;
    const int gid = lane >> 2, tig = lane & 3;
    uint32_t a_base[2], b_base[2];
#pragma unroll
    for (int mt = 0; mt < 2; mt++)
        a_base[mt] = (uint32_t)(m0w + mt * 16 + (lane & 15)) * 64 + ((uint32_t)(lane >> 4) << 4);
#pragma unroll
    for (int p = 0; p < 2; p++)
        b_base[p] = (uint32_t)(n0w + p * 16 + (lane & 7) + ((lane >> 3) & 1) * 8) * 64 +
                    ((uint32_t)(lane >> 4) << 4);

    float acc[2][4][4];
#pragma unroll
    for (int mt = 0; mt < 2; mt++)
#pragma unroll
        for (int nf = 0; nf < 4; nf++)
#pragma unroll
            for (int r = 0; r < 4; r++) acc[mt][nf][r] = 0.f;

    float4 xreg[4], wreg[2];
#pragma unroll
    for (int q = 0; q < 4; q++) xreg[q] = *reinterpret_cast<const float4*>(Xg + 4 * q);
    wreg[0] = *reinterpret_cast<const float4*>(Wg);
    wreg[1] = *reinterpret_cast<const float4*>(Wg + 4);

    for (int t = 0; t < KTILES; t++) {
        const uint32_t sb = sbase + (uint32_t)(t & 1) * STAGE_BYTES;

        {
            uint2 h0, l0, h1, l1;
            split4(xreg[0], SCALE_X, h0, l0);
            split4(xreg[1], SCALE_X, h1, l1);
            sts16(sb + ST_XHI + xo1, make_uint4(h0.x, h0.y, h1.x, h1.y));
            sts16(sb + ST_XLO + xo1, make_uint4(l0.x, l0.y, l1.x, l1.y));
            split4(xreg[2], SCALE_X, h0, l0);
            split4(xreg[3], SCALE_X, h1, l1);
            sts16(sb + ST_XHI + xo2, make_uint4(h0.x, h0.y, h1.x, h1.y));
            sts16(sb + ST_XLO + xo2, make_uint4(l0.x, l0.y, l1.x, l1.y));
            split4(wreg[0], SCALE_W, h0, l0);
            split4(wreg[1], SCALE_W, h1, l1);
            sts16(sb + ST_WHI + wo, make_uint4(h0.x, h0.y, h1.x, h1.y));
            sts16(sb + ST_WLO + wo, make_uint4(l0.x, l0.y, l1.x, l1.y));
        }
        __syncthreads();

        if (t + 1 < KTILES) {
            const float* xg = Xg + (t + 1) * BK;
            const float* wg = Wg + (t + 1) * BK;
#pragma unroll
            for (int q = 0; q < 4; q++) xreg[q] = *reinterpret_cast<const float4*>(xg + 4 * q);
            wreg[0] = *reinterpret_cast<const float4*>(wg);
            wreg[1] = *reinterpret_cast<const float4*>(wg + 4);
        }

#pragma unroll
        for (int s = 0; s < 2; s++) {
            const uint32_t ko = (uint32_t)s * 32;
            uint32_t ahi[2][4], alo[2][4], bhi[4][2], blo[4][2], r[4];
#pragma unroll
            for (int mt = 0; mt < 2; mt++) {
                ldsm4(ahi[mt], sb + ST_XHI + swz64(a_base[mt] + ko));
                ldsm4(alo[mt], sb + ST_XLO + swz64(a_base[mt] + ko));
            }
#pragma unroll
            for (int p = 0; p < 2; p++) {
                ldsm4(r, sb + ST_WHI + swz64(b_base[p] + ko));
                bhi[2 * p + 0][0] = r[0]; bhi[2 * p + 0][1] = r[2];
                bhi[2 * p + 1][0] = r[1]; bhi[2 * p + 1][1] = r[3];
                ldsm4(r, sb + ST_WLO + swz64(b_base[p] + ko));
                blo[2 * p + 0][0] = r[0]; blo[2 * p + 0][1] = r[2];
                blo[2 * p + 1][0] = r[1]; blo[2 * p + 1][1] = r[3];
            }
#pragma unroll
            for (int mt = 0; mt < 2; mt++)
#pragma unroll
                for (int nf = 0; nf < 4; nf++) {
                    mma16(acc[mt][nf], ahi[mt], bhi[nf]);
                    mma16(acc[mt][nf], ahi[mt], blo[nf]);
                    mma16(acc[mt][nf], alo[mt], bhi[nf]);
                }
        }
    }

    __syncthreads();

    float* lg = reinterpret_cast<float*>(smem_raw);
#pragma unroll
    for (int mt = 0; mt < 2; mt++)
#pragma unroll
        for (int nf = 0; nf < 4; nf++) {
            const int col = n0w + nf * 8 + 2 * tig;
            const int row = m0w + mt * 16 + gid;
            *reinterpret_cast<float2*>(lg + row * 66 + col) =
                make_float2(acc[mt][nf][0] * ISCALE, acc[mt][nf][1] * ISCALE);
            *reinterpret_cast<float2*>(lg + (row + 8) * 66 + col) =
                make_float2(acc[mt][nf][2] * ISCALE, acc[mt][nf][3] * ISCALE);
        }
    __syncthreads();

    if (tid < BM) {
        float* row = lg + tid * 66;
        float vals[TOPK + 1];
        int   idxs[TOPK + 1];
#pragma unroll
        for (int r = 0; r < TOPK + 1; r++) {      // top-9 for gap check
            float best = -__int_as_float(0x7f800000);
            int bi = 0;
            for (int e = 0; e < N_EXP; e++) {
                float v = row[e];
                if (v > best) { best = v; bi = e; }
            }
            vals[r] = best;
            idxs[r] = bi;
            row[bi] = -__int_as_float(0x7f800000);
        }
        float mingap = vals[0] - vals[1];
#pragma unroll
        for (int r = 1; r < TOPK; r++) mingap = fminf(mingap, vals[r] - vals[r + 1]);

        const long long gtok = block_m + tid;
        g_tok[block_m + tid] = (mingap < EPS) ? (int)gtok : -1;   // deterministic

        const float m0f = vals[0];
        float wv[TOPK];
        float s = 0.f;
#pragma unroll
        for (int r = 0; r < TOPK; r++) { wv[r] = __expf(vals[r] - m0f); s += wv[r]; }
        const float inv = 1.f / s;
#pragma unroll
        for (int r = 0; r < TOPK; r++) {
            out[gtok * TOPK + r] = wv[r] * inv;
            out[(long long)T * TOPK + gtok * TOPK + r] = (float)idxs[r];
        }
    }
}

// compact marked tokens into a dense list. List ORDER is nondeterministic but
// irrelevant: each token's eventual writes depend only on the token id.
__global__ __launch_bounds__(256, 8)
void moe_gate_compact() {
    const int idx = blockIdx.x * 256 + threadIdx.x;
    const int v = g_tok[idx];
    if (v >= 0) {
        int pos = atomicAdd(&g_cnt, 1);
        if (pos < FIX_GRID) g_list[pos] = v;
    }
}

// exact slow path: one block per dense token; all chains in ONE wave.
// X staged in smem, W software-pipelined; fmaf ORDER identical to R6/R8/R9.
__global__ __launch_bounds__(64, 4)
void moe_gate_fixup(const float* __restrict__ X, const float* __restrict__ W,
                    float* __restrict__ out, int T) {
    __shared__ float xs[H_DIM];
    __shared__ float lg[N_EXP];
    const int n = g_cnt < FIX_GRID ? g_cnt : FIX_GRID;
    if (blockIdx.x >= n) return;
    const int tok = g_list[blockIdx.x];

    const int e = threadIdx.x;           // 64 threads = 64 experts
    {
        const float4* xg = reinterpret_cast<const float4*>(X + (size_t)tok * H_DIM);
        float4* xd = reinterpret_cast<float4*>(xs);
#pragma unroll
        for (int i = 0; i < H_DIM / 4 / 64; i++) xd[e + i * 64] = xg[e + i * 64];
    }
    __syncthreads();

    float acc = 0.f;
    float4 bufA[16], bufB[16];
    const float4* w4 = reinterpret_cast<const float4*>(W + (size_t)e * H_DIM);
#pragma unroll
    for (int j = 0; j < 16; j++) bufA[j] = w4[j];

    for (int c = 0; c < 32; c += 2) {        // 64-k chunks, ping-pong prefetch
        if (c + 1 < 32) {
#pragma unroll
            for (int j = 0; j < 16; j++) bufB[j] = w4[(c + 1) * 16 + j];
        }
        const float4* xc = reinterpret_cast<const float4*>(xs + c * 64);
#pragma unroll
        for (int j = 0; j < 16; j++) {       // strict sequential chain
            float4 xv = xc[j];
            acc = fmaf(xv.x, bufA[j].x, acc);
            acc = fmaf(xv.y, bufA[j].y, acc);
            acc = fmaf(xv.z, bufA[j].z, acc);
            acc = fmaf(xv.w, bufA[j].w, acc);
        }
        if (c + 2 < 32) {
#pragma unroll
            for (int j = 0; j < 16; j++) bufA[j] = w4[(c + 2) * 16 + j];
        }
        const float4* xc2 = reinterpret_cast<const float4*>(xs + (c + 1) * 64);
#pragma unroll
        for (int j = 0; j < 16; j++) {
            float4 xv = xc2[j];
            acc = fmaf(xv.x, bufB[j].x, acc);
            acc = fmaf(xv.y, bufB[j].y, acc);
            acc = fmaf(xv.z, bufB[j].z, acc);
            acc = fmaf(xv.w, bufB[j].w, acc);
        }
    }
    lg[e] = acc;
    __syncthreads();

    if (e == 0) {
        float vals[TOPK];
        int   idxs[TOPK];
#pragma unroll
        for (int r = 0; r < TOPK; r++) {
            float best = -__int_as_float(0x7f800000);
            int bi = 0;
            for (int q = 0; q < N_EXP; q++) {
                float v = lg[q];
                if (v > best) { best = v; bi = q; }
            }
            vals[r] = best;
            idxs[r] = bi;
            lg[bi] = -__int_as_float(0x7f800000);
        }
        const float m0f = vals[0];
        float wv[TOPK];
        float sm = 0.f;
#pragma unroll
        for (int r = 0; r < TOPK; r++) { wv[r] = __expf(vals[r] - m0f); sm += wv[r]; }
        const float inv = 1.f / sm;
#pragma unroll
        for (int r = 0; r < TOPK; r++) {
            out[(long long)tok * TOPK + r] = wv[r] * inv;
            out[(long long)T * TOPK + (long long)tok * TOPK + r] = (float)idxs[r];
        }
    }
}

extern "C" void kernel_launch(void* const* d_in, const int* in_sizes, int n_in,
                              void* d_out, int out_size) {
    const float* X = (const float*)d_in[0];   // hidden_states [4,4096,2048] fp32
    const float* W = (const float*)d_in[1];   // weight [64,2048] fp32
    float* out = (float*)d_out;

    const int T = in_sizes[0] / H_DIM;        // 16384
    const int grid = T / BM;                  // 128

    cudaFuncSetAttribute(moe_gate_fast,
                         cudaFuncAttributeMaxDynamicSharedMemorySize, SMEM_BYTES);
    moe_gate_fast<<<grid, NTHREADS, SMEM_BYTES>>>(X, W, out, T);
    moe_gate_compact<<<T / 256, 256>>>();
    moe_gate_fixup<<<FIX_GRID, 64>>>(X, W, out, T);
}

// round 11
// speedup vs baseline: 2.0136x; 1.0303x over previous
#include <cuda_runtime.h>
#include <cuda_fp16.h>
#include <cstdint>

// MoEGate hybrid, fp16x3 (Ootomo-style split) tensor fast path + exact fixup:
//   fast (512 thr, 16 warps, warp tile 32x16): logits = X @ W^T via f16 MMA
//   computing hi*hi + hi*lo + lo*hi with fp32 accumulate (operands pre-scaled
//   2^4 / 2^6; logits unscaled by 2^-10 exactly). top-9 gap check marks
//   ambiguous tokens (adjacent gap < EPS) in g_tok.
//   compact: dense list of marked tokens (list order irrelevant to output).
//   fixup: ONE BLOCK PER DENSE TOKEN -> all exact sequential-k fp32 chains
//   (reference-matching order, proven R6/R8/R9/R10) run in a single chain-wave.
// Output (float32): [T*8] topk weights, then [T*8] topk indices (as float).

#define H_DIM 2048
#define N_EXP 64
#define TOPK  8
#define BM    128
#define BK    32
#define KTILES (H_DIM / BK)       // 64
#define NTHREADS 512
#define EPS   2e-4f
#define SCALE_X 16.0f
#define SCALE_W 64.0f
#define ISCALE  (1.0f / 1024.0f)

#define ST_XHI 0
#define ST_XLO 8192
#define ST_WHI 16384
#define ST_WLO 20480
#define STAGE_BYTES 24576
#define SMEM_BYTES (2 * STAGE_BYTES)   // 49152

#define FIX_GRID 2048                  // upper bound on ambiguous tokens

__device__ int g_tok[16384];           // per-token flag: token id or -1
__device__ int g_list[FIX_GRID];       // compacted ambiguous tokens
__device__ int g_cnt;                  // compacted count

static __device__ __forceinline__ uint32_t smem_u32(const void* p) {
    uint32_t a;
    asm("{ .reg .u64 t; cvta.to.shared.u64 t, %1; cvt.u32.u64 %0, t; }" : "=r"(a) : "l"(p));
    return a;
}
static __device__ __forceinline__ uint32_t swz64(uint32_t off) {   // SW64 (64B rows)
    return off ^ ((off >> 3) & 0x30);
}
static __device__ __forceinline__ void sts16(uint32_t addr, uint4 v) {
    asm volatile("st.shared.v4.b32 [%0], {%1,%2,%3,%4};"
                 :: "r"(addr), "r"(v.x), "r"(v.y), "r"(v.z), "r"(v.w) : "memory");
}
static __device__ __forceinline__ void sts8(uint32_t addr, uint2 v) {
    asm volatile("st.shared.v2.b32 [%0], {%1,%2};"
                 :: "r"(addr), "r"(v.x), "r"(v.y) : "memory");
}
static __device__ __forceinline__ void ldsm4(uint32_t r[4], uint32_t addr) {
    asm volatile("ldmatrix.sync.aligned.m8n8.x4.shared.b16 {%0,%1,%2,%3}, [%4];"
                 : "=r"(r[0]), "=r"(r[1]), "=r"(r[2]), "=r"(r[3]) : "r"(addr));
}
static __device__ __forceinline__ uint32_t packh2(__half a, __half b) {
    return (uint32_t)__half_as_ushort(a) | ((uint32_t)__half_as_ushort(b) << 16);
}
static __device__ __forceinline__ void split4(float4 v, float s, uint2& h, uint2& l) {
    float x0 = v.x * s, x1 = v.y * s, x2 = v.z * s, x3 = v.w * s;
    __half h0 = __float2half_rn(x0), h1 = __float2half_rn(x1);
    __half h2 = __float2half_rn(x2), h3 = __float2half_rn(x3);
    __half l0 = __float2half_rn(x0 - __half2float(h0));
    __half l1 = __float2half_rn(x1 - __half2float(h1));
    __half l2 = __float2half_rn(x2 - __half2float(h2));
    __half l3 = __float2half_rn(x3 - __half2float(h3));
    h = make_uint2(packh2(h0, h1), packh2(h2, h3));
    l = make_uint2(packh2(l0, l1), packh2(l2, l3));
}
static __device__ __forceinline__ void mma16(float c[4], const uint32_t a[4],
                                             const uint32_t b[2]) {
    asm volatile(
        "mma.sync.aligned.m16n8k16.row.col.f32.f16.f16.f32 "
        "{%0,%1,%2,%3}, {%4,%5,%6,%7}, {%8,%9}, {%0,%1,%2,%3};"
        : "+f"(c[0]), "+f"(c[1]), "+f"(c[2]), "+f"(c[3])
        : "r"(a[0]), "r"(a[1]), "r"(a[2]), "r"(a[3]), "r"(b[0]), "r"(b[1]));
}

__global__ __launch_bounds__(NTHREADS, 1)
void moe_gate_fast(const float* __restrict__ X, const float* __restrict__ W,
                   float* __restrict__ out, int T) {
    extern __shared__ char smem_raw[];
    const uint32_t sbase = smem_u32(smem_raw);
    const int tid = threadIdx.x;
    const int block_m = blockIdx.x * BM;

    // counter reset for the compact kernel (kernel boundary orders it).
    if (blockIdx.x == 0 && tid == 0) g_cnt = 0;

    // ---- loader mapping (512 threads) ----
    const int xrow = tid >> 2, xk8 = (tid & 3) * 8;   // X: 8 floats/thread
    const int wrow = tid >> 3, wk4 = (tid & 7) * 4;   // W: 4 floats/thread
    const float* Xg = X + (size_t)(block_m + xrow) * H_DIM + xk8;
    const float* Wg = W + (size_t)wrow * H_DIM + wk4;
    const uint32_t xo = swz64((uint32_t)xrow * 64 + (uint32_t)xk8 * 2);   // 16B
    const uint32_t wo = swz64((uint32_t)wrow * 64 + (uint32_t)wk4 * 2);   // 8B

    // ---- MMA mapping: 16 warps = 4(M) x 4(N), warp tile 32x16 ----
    const int wid = tid >> 5, lane = tid & 31;
    const int m0w = (wid & 3) * 32, n0w = (wid >> 2) * 16;
    const int gid = lane >> 2, tig = lane & 3;
    uint32_t a_base[2];
#pragma unroll
    for (int mt = 0; mt < 2; mt++)
        a_base[mt] = (uint32_t)(m0w + mt * 16 + (lane & 15)) * 64 + ((uint32_t)(lane >> 4) << 4);
    const uint32_t b_base =
        (uint32_t)(n0w + (lane & 7) + ((lane >> 3) & 1) * 8) * 64 + ((uint32_t)(lane >> 4) << 4);

    float acc[2][2][4];
#pragma unroll
    for (int mt = 0; mt < 2; mt++)
#pragma unroll
        for (int nf = 0; nf < 2; nf++)
#pragma unroll
            for (int r = 0; r < 4; r++) acc[mt][nf][r] = 0.f;

    float4 xreg[2], wreg;
    xreg[0] = *reinterpret_cast<const float4*>(Xg);
    xreg[1] = *reinterpret_cast<const float4*>(Xg + 4);
    wreg    = *reinterpret_cast<const float4*>(Wg);

    for (int t = 0; t < KTILES; t++) {
        const uint32_t sb = sbase + (uint32_t)(t & 1) * STAGE_BYTES;

        {   // split + store current tile
            uint2 h0, l0, h1, l1;
            split4(xreg[0], SCALE_X, h0, l0);
            split4(xreg[1], SCALE_X, h1, l1);
            sts16(sb + ST_XHI + xo, make_uint4(h0.x, h0.y, h1.x, h1.y));
            sts16(sb + ST_XLO + xo, make_uint4(l0.x, l0.y, l1.x, l1.y));
            split4(wreg, SCALE_W, h0, l0);
            sts8(sb + ST_WHI + wo, h0);
            sts8(sb + ST_WLO + wo, l0);
        }
        __syncthreads();

        if (t + 1 < KTILES) {   // prefetch next tile
            const float* xg = Xg + (t + 1) * BK;
            const float* wg = Wg + (t + 1) * BK;
            xreg[0] = *reinterpret_cast<const float4*>(xg);
            xreg[1] = *reinterpret_cast<const float4*>(xg + 4);
            wreg    = *reinterpret_cast<const float4*>(wg);
        }

#pragma unroll
        for (int s = 0; s < 2; s++) {          // 2 k16-steps per tile
            const uint32_t ko = (uint32_t)s * 32;
            uint32_t ahi[2][4], alo[2][4], bhi[2][2], blo[2][2], r[4];
#pragma unroll
            for (int mt = 0; mt < 2; mt++) {
                ldsm4(ahi[mt], sb + ST_XHI + swz64(a_base[mt] + ko));
                ldsm4(alo[mt], sb + ST_XLO + swz64(a_base[mt] + ko));
            }
            ldsm4(r, sb + ST_WHI + swz64(b_base + ko));
            bhi[0][0] = r[0]; bhi[0][1] = r[2];
            bhi[1][0] = r[1]; bhi[1][1] = r[3];
            ldsm4(r, sb + ST_WLO + swz64(b_base + ko));
            blo[0][0] = r[0]; blo[0][1] = r[2];
            blo[1][0] = r[1]; blo[1][1] = r[3];
#pragma unroll
            for (int mt = 0; mt < 2; mt++)
#pragma unroll
                for (int nf = 0; nf < 2; nf++) {
                    mma16(acc[mt][nf], ahi[mt], bhi[nf]);   // hi*hi
                    mma16(acc[mt][nf], ahi[mt], blo[nf]);   // hi*lo
                    mma16(acc[mt][nf], alo[mt], bhi[nf]);   // lo*hi
                }
        }
    }

    __syncthreads();

    // logits[128][66] in smem (unscale by 2^-10)
    float* lg = reinterpret_cast<float*>(smem_raw);
#pragma unroll
    for (int mt = 0; mt < 2; mt++)
#pragma unroll
        for (int nf = 0; nf < 2; nf++) {
            const int col = n0w + nf * 8 + 2 * tig;
            const int row = m0w + mt * 16 + gid;
            *reinterpret_cast<float2*>(lg + row * 66 + col) =
                make_float2(acc[mt][nf][0] * ISCALE, acc[mt][nf][1] * ISCALE);
            *reinterpret_cast<float2*>(lg + (row + 8) * 66 + col) =
                make_float2(acc[mt][nf][2] * ISCALE, acc[mt][nf][3] * ISCALE);
        }
    __syncthreads();

    if (tid < BM) {
        float* row = lg + tid * 66;
        float vals[TOPK + 1];
        int   idxs[TOPK + 1];
#pragma unroll
        for (int r = 0; r < TOPK + 1; r++) {      // top-9 for gap check
            float best = -__int_as_float(0x7f800000);
            int bi = 0;
            for (int e = 0; e < N_EXP; e++) {
                float v = row[e];
                if (v > best) { best = v; bi = e; }
            }
            vals[r] = best;
            idxs[r] = bi;
            row[bi] = -__int_as_float(0x7f800000);
        }
        float mingap = vals[0] - vals[1];
#pragma unroll
        for (int r = 1; r < TOPK; r++) mingap = fminf(mingap, vals[r] - vals[r + 1]);

        const long long gtok = block_m + tid;
        g_tok[block_m + tid] = (mingap < EPS) ? (int)gtok : -1;   // deterministic

        const float m0f = vals[0];
        float wv[TOPK];
        float s = 0.f;
#pragma unroll
        for (int r = 0; r < TOPK; r++) { wv[r] = __expf(vals[r] - m0f); s += wv[r]; }
        const float inv = 1.f / s;
#pragma unroll
        for (int r = 0; r < TOPK; r++) {
            out[gtok * TOPK + r] = wv[r] * inv;
            out[(long long)T * TOPK + gtok * TOPK + r] = (float)idxs[r];
        }
    }
}

// compact marked tokens into a dense list. List ORDER is nondeterministic but
// irrelevant: each token's eventual writes depend only on the token id.
__global__ __launch_bounds__(256, 8)
void moe_gate_compact() {
    const int idx = blockIdx.x * 256 + threadIdx.x;
    const int v = g_tok[idx];
    if (v >= 0) {
        int pos = atomicAdd(&g_cnt, 1);
        if (pos < FIX_GRID) g_list[pos] = v;
    }
}

// exact slow path: one block per dense token; all chains in ONE wave.
// X staged in smem, W software-pipelined; fmaf ORDER identical to R6/R8/R9/R10.
__global__ __launch_bounds__(64, 4)
void moe_gate_fixup(const float* __restrict__ X, const float* __restrict__ W,
                    float* __restrict__ out, int T) {
    __shared__ float xs[H_DIM];
    __shared__ float lg[N_EXP];
    const int n = g_cnt < FIX_GRID ? g_cnt : FIX_GRID;
    if (blockIdx.x >= n) return;
    const int tok = g_list[blockIdx.x];

    const int e = threadIdx.x;           // 64 threads = 64 experts
    {
        const float4* xg = reinterpret_cast<const float4*>(X + (size_t)tok * H_DIM);
        float4* xd = reinterpret_cast<float4*>(xs);
#pragma unroll
        for (int i = 0; i < H_DIM / 4 / 64; i++) xd[e + i * 64] = xg[e + i * 64];
    }
    __syncthreads();

    float acc = 0.f;
    float4 bufA[16], bufB[16];
    const float4* w4 = reinterpret_cast<const float4*>(W + (size_t)e * H_DIM);
#pragma unroll
    for (int j = 0; j < 16; j++) bufA[j] = w4[j];

    for (int c = 0; c < 32; c += 2) {        // 64-k chunks, ping-pong prefetch
        if (c + 1 < 32) {
#pragma unroll
            for (int j = 0; j < 16; j++) bufB[j] = w4[(c + 1) * 16 + j];
        }
        const float4* xc = reinterpret_cast<const float4*>(xs + c * 64);
#pragma unroll
        for (int j = 0; j < 16; j++) {       // strict sequential chain
            float4 xv = xc[j];
            acc = fmaf(xv.x, bufA[j].x, acc);
            acc = fmaf(xv.y, bufA[j].y, acc);
            acc = fmaf(xv.z, bufA[j].z, acc);
            acc = fmaf(xv.w, bufA[j].w, acc);
        }
        if (c + 2 < 32) {
#pragma unroll
            for (int j = 0; j < 16; j++) bufA[j] = w4[(c + 2) * 16 + j];
        }
        const float4* xc2 = reinterpret_cast<const float4*>(xs + (c + 1) * 64);
#pragma unroll
        for (int j = 0; j < 16; j++) {
            float4 xv = xc2[j];
            acc = fmaf(xv.x, bufB[j].x, acc);
            acc = fmaf(xv.y, bufB[j].y, acc);
            acc = fmaf(xv.z, bufB[j].z, acc);
            acc = fmaf(xv.w, bufB[j].w, acc);
        }
    }
    lg[e] = acc;
    __syncthreads();

    if (e == 0) {
        float vals[TOPK];
        int   idxs[TOPK];
#pragma unroll
        for (int r = 0; r < TOPK; r++) {
            float best = -__int_as_float(0x7f800000);
            int bi = 0;
            for (int q = 0; q < N_EXP; q++) {
                float v = lg[q];
                if (v > best) { best = v; bi = q; }
            }
            vals[r] = best;
            idxs[r] = bi;
            lg[bi] = -__int_as_float(0x7f800000);
        }
        const float m0f = vals[0];
        float wv[TOPK];
        float sm = 0.f;
#pragma unroll
        for (int r = 0; r < TOPK; r++) { wv[r] = __expf(vals[r] - m0f); sm += wv[r]; }
        const float inv = 1.f / sm;
#pragma unroll
        for (int r = 0; r < TOPK; r++) {
            out[(long long)tok * TOPK + r] = wv[r] * inv;
            out[(long long)T * TOPK + (long long)tok * TOPK + r] = (float)idxs[r];
        }
    }
}

extern "C" void kernel_launch(void* const* d_in, const int* in_sizes, int n_in,
                              void* d_out, int out_size) {
    const float* X = (const float*)d_in[0];   // hidden_states [4,4096,2048] fp32
    const float* W = (const float*)d_in[1];   // weight [64,2048] fp32
    float* out = (float*)d_out;

    const int T = in_sizes[0] / H_DIM;        // 16384
    const int grid = T / BM;                  // 128

    cudaFuncSetAttribute(moe_gate_fast,
                         cudaFuncAttributeMaxDynamicSharedMemorySize, SMEM_BYTES);
    moe_gate_fast<<<grid, NTHREADS, SMEM_BYTES>>>(X, W, out, T);
    moe_gate_compact<<<T / 256, 256>>>();
    moe_gate_fixup<<<FIX_GRID, 64>>>(X, W, out, T);
}

// round 12
// speedup vs baseline: 2.0866x; 1.0362x over previous
#include <cuda_runtime.h>
#include <cuda_fp16.h>
#include <cstdint>

// MoEGate hybrid, fp16x3 (Ootomo-style split) tensor fast path + exact fixup.
//   prep: split W (scaled by 2^6) into fp16 hi/lo arrays once per call; reset
//         ambiguous-token counter.
//   fast (512 thr, 16 warps, warp tile 32x16, BK=64): logits = X @ W^T via f16
//         MMA computing hi*hi + hi*lo + lo*hi with fp32 accumulate (X scaled by
//         2^4 at split; logits unscaled by 2^-10 exactly). top-9 gap check:
//         ambiguous tokens (adjacent gap < EPS) pushed to g_list via atomicAdd
//         (list order irrelevant: each token's writes depend only on token id).
//   fixup: ONE BLOCK PER DENSE TOKEN; exact sequential-k fp32 chains
//         (reference-matching order, proven R6/R8-R11) run in one chain-wave.
// Output (float32): [T*8] topk weights, then [T*8] topk indices (as float).

#define H_DIM 2048
#define N_EXP 64
#define TOPK  8
#define BM    128
#define BK    64
#define KTILES (H_DIM / BK)       // 32
#define NTHREADS 512
#define EPS   2e-4f
#define SCALE_X 16.0f
#define SCALE_W 64.0f
#define ISCALE  (1.0f / 1024.0f)

// smem stage (halfs, 128B rows, SW128 swizzle)
#define ST_XHI 0
#define ST_XLO 16384
#define ST_WHI 32768
#define ST_WLO 40960
#define STAGE_BYTES 49152
#define SMEM_BYTES (2 * STAGE_BYTES)   // 98304

#define FIX_GRID 2048

__device__ int    g_list[FIX_GRID];    // ambiguous tokens (dense)
__device__ int    g_cnt;               // count (reset by prep each call)
__device__ __half g_whi[N_EXP * H_DIM];
__device__ __half g_wlo[N_EXP * H_DIM];

static __device__ __forceinline__ uint32_t smem_u32(const void* p) {
    uint32_t a;
    asm("{ .reg .u64 t; cvta.to.shared.u64 t, %1; cvt.u32.u64 %0, t; }" : "=r"(a) : "l"(p));
    return a;
}
static __device__ __forceinline__ uint32_t swz(uint32_t off) {   // SW128 (128B rows)
    return off ^ ((off >> 3) & 0x70);
}
static __device__ __forceinline__ void sts16(uint32_t addr, uint4 v) {
    asm volatile("st.shared.v4.b32 [%0], {%1,%2,%3,%4};"
                 :: "r"(addr), "r"(v.x), "r"(v.y), "r"(v.z), "r"(v.w) : "memory");
}
static __device__ __forceinline__ void ldsm4(uint32_t r[4], uint32_t addr) {
    asm volatile("ldmatrix.sync.aligned.m8n8.x4.shared.b16 {%0,%1,%2,%3}, [%4];"
                 : "=r"(r[0]), "=r"(r[1]), "=r"(r[2]), "=r"(r[3]) : "r"(addr));
}
// packed split: hi = rn(f16x2), lo = rn(f16x2 of x - hi). Bit-identical per
// element to __float2half_rn-based splitting.
static __device__ __forceinline__ void split4p(float4 v, float s, uint32_t& h01,
                                               uint32_t& h23, uint32_t& l01,
                                               uint32_t& l23) {
    float x0 = v.x * s, x1 = v.y * s, x2 = v.z * s, x3 = v.w * s;
    asm("cvt.rn.f16x2.f32 %0, %1, %2;" : "=r"(h01) : "f"(x1), "f"(x0));
    asm("cvt.rn.f16x2.f32 %0, %1, %2;" : "=r"(h23) : "f"(x3), "f"(x2));
    __half2 hh01 = *reinterpret_cast<__half2*>(&h01);
    __half2 hh23 = *reinterpret_cast<__half2*>(&h23);
    float f0 = __half2float(hh01.x), f1 = __half2float(hh01.y);
    float f2 = __half2float(hh23.x), f3 = __half2float(hh23.y);
    asm("cvt.rn.f16x2.f32 %0, %1, %2;" : "=r"(l01) : "f"(x1 - f1), "f"(x0 - f0));
    asm("cvt.rn.f16x2.f32 %0, %1, %2;" : "=r"(l23) : "f"(x3 - f3), "f"(x2 - f2));
}
static __device__ __forceinline__ void mma16(float c[4], const uint32_t a[4],
                                             const uint32_t b[2]) {
    asm volatile(
        "mma.sync.aligned.m16n8k16.row.col.f32.f16.f16.f32 "
        "{%0,%1,%2,%3}, {%4,%5,%6,%7}, {%8,%9}, {%0,%1,%2,%3};"
        : "+f"(c[0]), "+f"(c[1]), "+f"(c[2]), "+f"(c[3])
        : "r"(a[0]), "r"(a[1]), "r"(a[2]), "r"(a[3]), "r"(b[0]), "r"(b[1]));
}

// prep: split W once (identical arithmetic to the old in-loop split) + reset g_cnt.
__global__ __launch_bounds__(256, 4)
void moe_gate_prep(const float* __restrict__ W) {
    if (blockIdx.x == 0 && threadIdx.x == 0) g_cnt = 0;
    const int base = (blockIdx.x * 256 + threadIdx.x) * 8;   // grid covers 64*2048
#pragma unroll
    for (int q = 0; q < 2; q++) {
        float4 v = *reinterpret_cast<const float4*>(W + base + 4 * q);
        uint32_t h01, h23, l01, l23;
        split4p(v, SCALE_W, h01, h23, l01, l23);
        *reinterpret_cast<uint2*>(&g_whi[base + 4 * q]) = make_uint2(h01, h23);
        *reinterpret_cast<uint2*>(&g_wlo[base + 4 * q]) = make_uint2(l01, l23);
    }
}

__global__ __launch_bounds__(NTHREADS, 1)
void moe_gate_fast(const float* __restrict__ X, const float* __restrict__ W,
                   float* __restrict__ out, int T) {
    extern __shared__ char smem_raw[];
    const uint32_t sbase = smem_u32(smem_raw);
    const int tid = threadIdx.x;
    const int block_m = blockIdx.x * BM;

    // ---- loader mapping ----
    const int xrow = tid >> 2, xk16 = (tid & 3) * 16;   // X: 16 floats/thread
    const int wrow = tid >> 3, wk8  = (tid & 7) * 8;    // W: 8 halves/thread (hi+lo)
    const float* Xg = X + (size_t)(block_m + xrow) * H_DIM + xk16;
    const __half* WgH = g_whi + (size_t)wrow * H_DIM + wk8;
    const __half* WgL = g_wlo + (size_t)wrow * H_DIM + wk8;
    const uint32_t xo = (uint32_t)xrow * 128 + (uint32_t)xk16 * 2;   // byte
    const uint32_t wo = swz((uint32_t)wrow * 128 + (uint32_t)wk8 * 2);

    // ---- MMA mapping: 16 warps = 4(M) x 4(N), warp tile 32x16 ----
    const int wid = tid >> 5, lane = tid & 31;
    const int m0w = (wid & 3) * 32, n0w = (wid >> 2) * 16;
    const int gid = lane >> 2, tig = lane & 3;
    uint32_t a_base[2];
#pragma unroll
    for (int mt = 0; mt < 2; mt++)
        a_base[mt] = (uint32_t)(m0w + mt * 16 + (lane & 15)) * 128 + ((uint32_t)(lane >> 4) << 4);
    const uint32_t b_base =
        (uint32_t)(n0w + (lane & 7) + ((lane >> 3) & 1) * 8) * 128 + ((uint32_t)(lane >> 4) << 4);

    float acc[2][2][4];
#pragma unroll
    for (int mt = 0; mt < 2; mt++)
#pragma unroll
        for (int nf = 0; nf < 2; nf++)
#pragma unroll
            for (int r = 0; r < 4; r++) acc[mt][nf][r] = 0.f;

    float4 xreg[4];
    uint4  wh, wl;
#pragma unroll
    for (int q = 0; q < 4; q++) xreg[q] = *reinterpret_cast<const float4*>(Xg + 4 * q);
    wh = *reinterpret_cast<const uint4*>(WgH);
    wl = *reinterpret_cast<const uint4*>(WgL);

    for (int t = 0; t < KTILES; t++) {
        const uint32_t sb = sbase + (uint32_t)(t & 1) * STAGE_BYTES;

        {   // split X + store; store pre-split W directly
            uint32_t h01, h23, l01, l23, g01, g23, m01, m23;
            split4p(xreg[0], SCALE_X, h01, h23, l01, l23);
            split4p(xreg[1], SCALE_X, g01, g23, m01, m23);
            sts16(sb + ST_XHI + swz(xo), make_uint4(h01, h23, g01, g23));
            sts16(sb + ST_XLO + swz(xo), make_uint4(l01, l23, m01, m23));
            split4p(xreg[2], SCALE_X, h01, h23, l01, l23);
            split4p(xreg[3], SCALE_X, g01, g23, m01, m23);
            sts16(sb + ST_XHI + swz(xo + 16), make_uint4(h01, h23, g01, g23));
            sts16(sb + ST_XLO + swz(xo + 16), make_uint4(l01, l23, m01, m23));
            sts16(sb + ST_WHI + wo, wh);
            sts16(sb + ST_WLO + wo, wl);
        }
        __syncthreads();

        if (t + 1 < KTILES) {   // prefetch next tile
            const float* xg = Xg + (t + 1) * BK;
#pragma unroll
            for (int q = 0; q < 4; q++) xreg[q] = *reinterpret_cast<const float4*>(xg + 4 * q);
            wh = *reinterpret_cast<const uint4*>(WgH + (t + 1) * BK);
            wl = *reinterpret_cast<const uint4*>(WgL + (t + 1) * BK);
        }

#pragma unroll
        for (int s = 0; s < 4; s++) {          // 4 k16-steps per tile
            const uint32_t ko = (uint32_t)s * 32;
            uint32_t ahi[2][4], alo[2][4], bhi[2][2], blo[2][2], r[4];
#pragma unroll
            for (int mt = 0; mt < 2; mt++) {
                ldsm4(ahi[mt], sb + ST_XHI + swz(a_base[mt] + ko));
                ldsm4(alo[mt], sb + ST_XLO + swz(a_base[mt] + ko));
            }
            ldsm4(r, sb + ST_WHI + swz(b_base + ko));
            bhi[0][0] = r[0]; bhi[0][1] = r[2];
            bhi[1][0] = r[1]; bhi[1][1] = r[3];
            ldsm4(r, sb + ST_WLO + swz(b_base + ko));
            blo[0][0] = r[0]; blo[0][1] = r[2];
            blo[1][0] = r[1]; blo[1][1] = r[3];
#pragma unroll
            for (int mt = 0; mt < 2; mt++)
#pragma unroll
                for (int nf = 0; nf < 2; nf++) {
                    mma16(acc[mt][nf], ahi[mt], bhi[nf]);   // hi*hi
                    mma16(acc[mt][nf], ahi[mt], blo[nf]);   // hi*lo
                    mma16(acc[mt][nf], alo[mt], bhi[nf]);   // lo*hi
                }
        }
    }

    __syncthreads();

    // logits[128][66] in smem (unscale by 2^-10)
    float* lg = reinterpret_cast<float*>(smem_raw);
#pragma unroll
    for (int mt = 0; mt < 2; mt++)
#pragma unroll
        for (int nf = 0; nf < 2; nf++) {
            const int col = n0w + nf * 8 + 2 * tig;
            const int row = m0w + mt * 16 + gid;
            *reinterpret_cast<float2*>(lg + row * 66 + col) =
                make_float2(acc[mt][nf][0] * ISCALE, acc[mt][nf][1] * ISCALE);
            *reinterpret_cast<float2*>(lg + (row + 8) * 66 + col) =
                make_float2(acc[mt][nf][2] * ISCALE, acc[mt][nf][3] * ISCALE);
        }
    __syncthreads();

    if (tid < BM) {
        float* row = lg + tid * 66;
        float vals[TOPK + 1];
        int   idxs[TOPK + 1];
#pragma unroll
        for (int r = 0; r < TOPK + 1; r++) {      // top-9 for gap check
            float best = -__int_as_float(0x7f800000);
            int bi = 0;
            for (int e = 0; e < N_EXP; e++) {
                float v = row[e];
                if (v > best) { best = v; bi = e; }
            }
            vals[r] = best;
            idxs[r] = bi;
            row[bi] = -__int_as_float(0x7f800000);
        }
        float mingap = vals[0] - vals[1];
#pragma unroll
        for (int r = 1; r < TOPK; r++) mingap = fminf(mingap, vals[r] - vals[r + 1]);

        const long long gtok = block_m + tid;
        if (mingap < EPS) {     // push to dense list (order irrelevant to output)
            int pos = atomicAdd(&g_cnt, 1);
            if (pos < FIX_GRID) g_list[pos] = (int)gtok;
        }

        const float m0f = vals[0];
        float wv[TOPK];
        float s = 0.f;
#pragma unroll
        for (int r = 0; r < TOPK; r++) { wv[r] = __expf(vals[r] - m0f); s += wv[r]; }
        const float inv = 1.f / s;
#pragma unroll
        for (int r = 0; r < TOPK; r++) {
            out[gtok * TOPK + r] = wv[r] * inv;
            out[(long long)T * TOPK + gtok * TOPK + r] = (float)idxs[r];
        }
    }
}

// exact slow path: one block per dense token; all chains in ONE wave.
// X staged in smem, W software-pipelined; fmaf ORDER identical to R6/R8-R11.
__global__ __launch_bounds__(64, 4)
void moe_gate_fixup(const float* __restrict__ X, const float* __restrict__ W,
                    float* __restrict__ out, int T) {
    __shared__ float xs[H_DIM];
    __shared__ float lg[N_EXP];
    const int n = g_cnt < FIX_GRID ? g_cnt : FIX_GRID;
    if (blockIdx.x >= n) return;
    const int tok = g_list[blockIdx.x];

    const int e = threadIdx.x;           // 64 threads = 64 experts
    {
        const float4* xg = reinterpret_cast<const float4*>(X + (size_t)tok * H_DIM);
        float4* xd = reinterpret_cast<float4*>(xs);
#pragma unroll
        for (int i = 0; i < H_DIM / 4 / 64; i++) xd[e + i * 64] = xg[e + i * 64];
    }
    __syncthreads();

    float acc = 0.f;
    float4 bufA[16], bufB[16];
    const float4* w4 = reinterpret_cast<const float4*>(W + (size_t)e * H_DIM);
#pragma unroll
    for (int j = 0; j < 16; j++) bufA[j] = w4[j];

    for (int c = 0; c < 32; c += 2) {        // 64-k chunks, ping-pong prefetch
        if (c + 1 < 32) {
#pragma unroll
            for (int j = 0; j < 16; j++) bufB[j] = w4[(c + 1) * 16 + j];
        }
        const float4* xc = reinterpret_cast<const float4*>(xs + c * 64);
#pragma unroll
        for (int j = 0; j < 16; j++) {       // strict sequential chain
            float4 xv = xc[j];
            acc = fmaf(xv.x, bufA[j].x, acc);
            acc = fmaf(xv.y, bufA[j].y, acc);
            acc = fmaf(xv.z, bufA[j].z, acc);
            acc = fmaf(xv.w, bufA[j].w, acc);
        }
        if (c + 2 < 32) {
#pragma unroll
            for (int j = 0; j < 16; j++) bufA[j] = w4[(c + 2) * 16 + j];
        }
        const float4* xc2 = reinterpret_cast<const float4*>(xs + (c + 1) * 64);
#pragma unroll
        for (int j = 0; j < 16; j++) {
            float4 xv = xc2[j];
            acc = fmaf(xv.x, bufB[j].x, acc);
            acc = fmaf(xv.y, bufB[j].y, acc);
            acc = fmaf(xv.z, bufB[j].z, acc);
            acc = fmaf(xv.w, bufB[j].w, acc);
        }
    }
    lg[e] = acc;
    __syncthreads();

    if (e == 0) {
        float vals[TOPK];
        int   idxs[TOPK];
#pragma unroll
        for (int r = 0; r < TOPK; r++) {
            float best = -__int_as_float(0x7f800000);
            int bi = 0;
            for (int q = 0; q < N_EXP; q++) {
                float v = lg[q];
                if (v > best) { best = v; bi = q; }
            }
            vals[r] = best;
            idxs[r] = bi;
            lg[bi] = -__int_as_float(0x7f800000);
        }
        const float m0f = vals[0];
        float wv[TOPK];
        float sm = 0.f;
#pragma unroll
        for (int r = 0; r < TOPK; r++) { wv[r] = __expf(vals[r] - m0f); sm += wv[r]; }
        const float inv = 1.f / sm;
#pragma unroll
        for (int r = 0; r < TOPK; r++) {
            out[(long long)tok * TOPK + r] = wv[r] * inv;
            out[(long long)T * TOPK + (long long)tok * TOPK + r] = (float)idxs[r];
        }
    }
}

extern "C" void kernel_launch(void* const* d_in, const int* in_sizes, int n_in,
                              void* d_out, int out_size) {
    const float* X = (const float*)d_in[0];   // hidden_states [4,4096,2048] fp32
    const float* W = (const float*)d_in[1];   // weight [64,2048] fp32
    float* out = (float*)d_out;

    const int T = in_sizes[0] / H_DIM;        // 16384
    const int grid = T / BM;                  // 128

    cudaFuncSetAttribute(moe_gate_fast,
                         cudaFuncAttributeMaxDynamicSharedMemorySize, SMEM_BYTES);
    moe_gate_prep<<<(N_EXP * H_DIM) / (256 * 8), 256>>>(W);
    moe_gate_fast<<<grid, NTHREADS, SMEM_BYTES>>>(X, W, out, T);
    moe_gate_fixup<<<FIX_GRID, 64>>>(X, W, out, T);
}

// round 13
// speedup vs baseline: 2.1643x; 1.0373x over previous
#include <cuda_runtime.h>
#include <cuda_fp16.h>
#include <cstdint>

// MoEGate hybrid, fp16x3 (Ootomo-style split) tensor fast path + exact fixup.
//   prep: split W (scaled 2^6) into fp16 hi/lo arrays once per call; reset cnt.
//   fast (512 thr, 16 warps, warp tile 32x16, BK=64, fully software-pipelined):
//     compute(t) overlaps cp.async W(t+1), split+STS X(t+1), LDG X(t+2).
//     logits = X @ W^T via f16 MMA (hi*hi + hi*lo + lo*hi, fp32 accumulate;
//     X scaled 2^4; logits unscaled by 2^-10 exactly). top-9 gap check pushes
//     ambiguous tokens (adjacent gap < EPS) to g_list (order output-invariant).
//   fixup: ONE BLOCK PER DENSE TOKEN; exact sequential-k fp32 chains
//     (reference-matching order, proven R6/R8-R12) in one chain-wave.
// Output (float32): [T*8] topk weights, then [T*8] topk indices (as float).

#define H_DIM 2048
#define N_EXP 64
#define TOPK  8
#define BM    128
#define BK    64
#define KTILES (H_DIM / BK)       // 32
#define NTHREADS 512
#define EPS   2e-4f
#define SCALE_X 16.0f
#define SCALE_W 64.0f
#define ISCALE  (1.0f / 1024.0f)

// smem stage (halfs, 128B rows, SW128 swizzle)
#define ST_XHI 0
#define ST_XLO 16384
#define ST_WHI 32768
#define ST_WLO 40960
#define STAGE_BYTES 49152
#define SMEM_BYTES (2 * STAGE_BYTES)   // 98304

#define FIX_GRID 2048

__device__ int    g_list[FIX_GRID];
__device__ int    g_cnt;
__device__ __half g_whi[N_EXP * H_DIM];
__device__ __half g_wlo[N_EXP * H_DIM];

static __device__ __forceinline__ uint32_t smem_u32(const void* p) {
    uint32_t a;
    asm("{ .reg .u64 t; cvta.to.shared.u64 t, %1; cvt.u32.u64 %0, t; }" : "=r"(a) : "l"(p));
    return a;
}
static __device__ __forceinline__ uint32_t swz(uint32_t off) {   // SW128
    return off ^ ((off >> 3) & 0x70);
}
static __device__ __forceinline__ void sts16(uint32_t addr, uint4 v) {
    asm volatile("st.shared.v4.b32 [%0], {%1,%2,%3,%4};"
                 :: "r"(addr), "r"(v.x), "r"(v.y), "r"(v.z), "r"(v.w) : "memory");
}
static __device__ __forceinline__ void cp16(uint32_t dst, const void* src) {
    asm volatile("cp.async.cg.shared.global [%0], [%1], 16;" :: "r"(dst), "l"(src) : "memory");
}
static __device__ __forceinline__ void ldsm4(uint32_t r[4], uint32_t addr) {
    asm volatile("ldmatrix.sync.aligned.m8n8.x4.shared.b16 {%0,%1,%2,%3}, [%4];"
                 : "=r"(r[0]), "=r"(r[1]), "=r"(r[2]), "=r"(r[3]) : "r"(addr));
}
// packed split: hi = rn(f16x2 of s*x), lo = rn(f16x2 of s*x - hi)
static __device__ __forceinline__ void split4p(float4 v, float s, uint32_t& h01,
                                               uint32_t& h23, uint32_t& l01,
                                               uint32_t& l23) {
    float x0 = v.x * s, x1 = v.y * s, x2 = v.z * s, x3 = v.w * s;
    asm("cvt.rn.f16x2.f32 %0, %1, %2;" : "=r"(h01) : "f"(x1), "f"(x0));
    asm("cvt.rn.f16x2.f32 %0, %1, %2;" : "=r"(h23) : "f"(x3), "f"(x2));
    __half2 hh01 = *reinterpret_cast<__half2*>(&h01);
    __half2 hh23 = *reinterpret_cast<__half2*>(&h23);
    float f0 = __half2float(hh01.x), f1 = __half2float(hh01.y);
    float f2 = __half2float(hh23.x), f3 = __half2float(hh23.y);
    asm("cvt.rn.f16x2.f32 %0, %1, %2;" : "=r"(l01) : "f"(x1 - f1), "f"(x0 - f0));
    asm("cvt.rn.f16x2.f32 %0, %1, %2;" : "=r"(l23) : "f"(x3 - f3), "f"(x2 - f2));
}
static __device__ __forceinline__ void mma16(float c[4], const uint32_t a[4],
                                             const uint32_t b[2]) {
    asm volatile(
        "mma.sync.aligned.m16n8k16.row.col.f32.f16.f16.f32 "
        "{%0,%1,%2,%3}, {%4,%5,%6,%7}, {%8,%9}, {%0,%1,%2,%3};"
        : "+f"(c[0]), "+f"(c[1]), "+f"(c[2]), "+f"(c[3])
        : "r"(a[0]), "r"(a[1]), "r"(a[2]), "r"(a[3]), "r"(b[0]), "r"(b[1]));
}

__global__ __launch_bounds__(256, 4)
void moe_gate_prep(const float* __restrict__ W) {
    if (blockIdx.x == 0 && threadIdx.x == 0) g_cnt = 0;
    const int base = (blockIdx.x * 256 + threadIdx.x) * 8;
#pragma unroll
    for (int q = 0; q < 2; q++) {
        float4 v = *reinterpret_cast<const float4*>(W + base + 4 * q);
        uint32_t h01, h23, l01, l23;
        split4p(v, SCALE_W, h01, h23, l01, l23);
        *reinterpret_cast<uint2*>(&g_whi[base + 4 * q]) = make_uint2(h01, h23);
        *reinterpret_cast<uint2*>(&g_wlo[base + 4 * q]) = make_uint2(l01, l23);
    }
}

__global__ __launch_bounds__(NTHREADS, 1)
void moe_gate_fast(const float* __restrict__ X, const float* __restrict__ W,
                   float* __restrict__ out, int T) {
    extern __shared__ char smem_raw[];
    const uint32_t sbase = smem_u32(smem_raw);
    const int tid = threadIdx.x;
    const int block_m = blockIdx.x * BM;

    // ---- loader mapping ----
    const int xrow = tid >> 2, xk16 = (tid & 3) * 16;   // X: 16 floats/thread
    const int wrow = tid >> 3, wk8  = (tid & 7) * 8;    // W: 8 halves/thread per buf
    const float*  Xg  = X + (size_t)(block_m + xrow) * H_DIM + xk16;
    const __half* WgH = g_whi + (size_t)wrow * H_DIM + wk8;
    const __half* WgL = g_wlo + (size_t)wrow * H_DIM + wk8;
    const uint32_t xo  = (uint32_t)xrow * 128 + (uint32_t)xk16 * 2;
    const uint32_t xs0 = swz(xo), xs1 = swz(xo + 16);
    const uint32_t wo  = swz((uint32_t)wrow * 128 + (uint32_t)wk8 * 2);

    // ---- MMA mapping: 16 warps = 4(M) x 4(N), warp tile 32x16 ----
    const int wid = tid >> 5, lane = tid & 31;
    const int m0w = (wid & 3) * 32, n0w = (wid >> 2) * 16;
    const int gid = lane >> 2, tig = lane & 3;
    uint32_t a_base[2];
#pragma unroll
    for (int mt = 0; mt < 2; mt++)
        a_base[mt] = (uint32_t)(m0w + mt * 16 + (lane & 15)) * 128 + ((uint32_t)(lane >> 4) << 4);
    const uint32_t b_base =
        (uint32_t)(n0w + (lane & 7) + ((lane >> 3) & 1) * 8) * 128 + ((uint32_t)(lane >> 4) << 4);

    float acc[2][2][4];
#pragma unroll
    for (int mt = 0; mt < 2; mt++)
#pragma unroll
        for (int nf = 0; nf < 2; nf++)
#pragma unroll
            for (int r = 0; r < 4; r++) acc[mt][nf][r] = 0.f;

    float4 xbufA[4], xbufB[4];

    // ---- prologue ----
    // X(0) -> regs -> split -> STS stage0 ; W(0) cp.async stage0 ; X(1) -> regs
#pragma unroll
    for (int q = 0; q < 4; q++) xbufA[q] = *reinterpret_cast<const float4*>(Xg + 4 * q);
    {
        const uint32_t sb = sbase;
        cp16(sb + ST_WHI + wo, WgH);
        cp16(sb + ST_WLO + wo, WgL);
        asm volatile("cp.async.commit_group;" ::: "memory");
        uint32_t h01, h23, l01, l23, g01, g23, m01, m23;
        split4p(xbufA[0], SCALE_X, h01, h23, l01, l23);
        split4p(xbufA[1], SCALE_X, g01, g23, m01, m23);
        sts16(sb + ST_XHI + xs0, make_uint4(h01, h23, g01, g23));
        sts16(sb + ST_XLO + xs0, make_uint4(l01, l23, m01, m23));
        split4p(xbufA[2], SCALE_X, h01, h23, l01, l23);
        split4p(xbufA[3], SCALE_X, g01, g23, m01, m23);
        sts16(sb + ST_XHI + xs1, make_uint4(h01, h23, g01, g23));
        sts16(sb + ST_XLO + xs1, make_uint4(l01, l23, m01, m23));
    }
#pragma unroll
    for (int q = 0; q < 4; q++) xbufB[q] = *reinterpret_cast<const float4*>(Xg + BK + 4 * q);
    asm volatile("cp.async.wait_group 0;" ::: "memory");
    __syncthreads();

    // ---- pipelined main loop ----
    // tile t: compute on stage[t&1]; overlap cp.async W(t+1) + split/STS X(t+1)
    // (regs xsplit) into stage[(t+1)&1] + LDG X(t+2) into xload.
    auto tile = [&](int t, float4* xsplit, float4* xload) {
        const uint32_t sb  = sbase + (uint32_t)(t & 1) * STAGE_BYTES;
        const uint32_t sb2 = sbase + (uint32_t)((t + 1) & 1) * STAGE_BYTES;
        const bool has1 = (t + 1 < KTILES);
        const bool has2 = (t + 2 < KTILES);

        if (has1) {   // W(t+1) straight to smem
            cp16(sb2 + ST_WHI + wo, WgH + (t + 1) * BK);
            cp16(sb2 + ST_WLO + wo, WgL + (t + 1) * BK);
        }
        asm volatile("cp.async.commit_group;" ::: "memory");

#pragma unroll
        for (int s = 0; s < 4; s++) {
            const uint32_t ko = (uint32_t)s * 32;
            uint32_t ahi[2][4], alo[2][4], bhi[2][2], blo[2][2], r[4];
#pragma unroll
            for (int mt = 0; mt < 2; mt++) {
                ldsm4(ahi[mt], sb + ST_XHI + swz(a_base[mt] + ko));
                ldsm4(alo[mt], sb + ST_XLO + swz(a_base[mt] + ko));
            }
            ldsm4(r, sb + ST_WHI + swz(b_base + ko));
            bhi[0][0] = r[0]; bhi[0][1] = r[2];
            bhi[1][0] = r[1]; bhi[1][1] = r[3];
            ldsm4(r, sb + ST_WLO + swz(b_base + ko));
            blo[0][0] = r[0]; blo[0][1] = r[2];
            blo[1][0] = r[1]; blo[1][1] = r[3];

            // interleaved next-tile work (hidden under the 12 MMAs below)
            if (s == 0 && has1) {
                uint32_t h01, h23, l01, l23, g01, g23, m01, m23;
                split4p(xsplit[0], SCALE_X, h01, h23, l01, l23);
                split4p(xsplit[1], SCALE_X, g01, g23, m01, m23);
                sts16(sb2 + ST_XHI + xs0, make_uint4(h01, h23, g01, g23));
                sts16(sb2 + ST_XLO + xs0, make_uint4(l01, l23, m01, m23));
            }
            if (s == 1 && has1) {
                uint32_t h01, h23, l01, l23, g01, g23, m01, m23;
                split4p(xsplit[2], SCALE_X, h01, h23, l01, l23);
                split4p(xsplit[3], SCALE_X, g01, g23, m01, m23);
                sts16(sb2 + ST_XHI + xs1, make_uint4(h01, h23, g01, g23));
                sts16(sb2 + ST_XLO + xs1, make_uint4(l01, l23, m01, m23));
            }
            if (s == 2 && has2) {
                const float* xg = Xg + (t + 2) * BK;
                xload[0] = *reinterpret_cast<const float4*>(xg);
                xload[1] = *reinterpret_cast<const float4*>(xg + 4);
            }
            if (s == 3 && has2) {
                const float* xg = Xg + (t + 2) * BK;
                xload[2] = *reinterpret_cast<const float4*>(xg + 8);
                xload[3] = *reinterpret_cast<const float4*>(xg + 12);
            }

#pragma unroll
            for (int mt = 0; mt < 2; mt++)
#pragma unroll
                for (int nf = 0; nf < 2; nf++) {
                    mma16(acc[mt][nf], ahi[mt], bhi[nf]);   // hi*hi
                    mma16(acc[mt][nf], ahi[mt], blo[nf]);   // hi*lo
                    mma16(acc[mt][nf], alo[mt], bhi[nf]);   // lo*hi
                }
        }
        asm volatile("cp.async.wait_group 0;" ::: "memory");
        __syncthreads();
    };

    for (int t = 0; t < KTILES; t += 2) {
        tile(t,     xbufB, xbufA);   // split X(t+1) from B, load X(t+2) into A
        tile(t + 1, xbufA, xbufB);   // split X(t+2) from A, load X(t+3) into B
    }

    // logits[128][66] in smem (unscale by 2^-10)
    float* lg = reinterpret_cast<float*>(smem_raw);
#pragma unroll
    for (int mt = 0; mt < 2; mt++)
#pragma unroll
        for (int nf = 0; nf < 2; nf++) {
            const int col = n0w + nf * 8 + 2 * tig;
            const int row = m0w + mt * 16 + gid;
            *reinterpret_cast<float2*>(lg + row * 66 + col) =
                make_float2(acc[mt][nf][0] * ISCALE, acc[mt][nf][1] * ISCALE);
            *reinterpret_cast<float2*>(lg + (row + 8) * 66 + col) =
                make_float2(acc[mt][nf][2] * ISCALE, acc[mt][nf][3] * ISCALE);
        }
    __syncthreads();

    if (tid < BM) {
        float* row = lg + tid * 66;
        float vals[TOPK + 1];
        int   idxs[TOPK + 1];
#pragma unroll
        for (int r = 0; r < TOPK + 1; r++) {      // top-9 for gap check
            float best = -__int_as_float(0x7f800000);
            int bi = 0;
            for (int e = 0; e < N_EXP; e++) {
                float v = row[e];
                if (v > best) { best = v; bi = e; }
            }
            vals[r] = best;
            idxs[r] = bi;
            row[bi] = -__int_as_float(0x7f800000);
        }
        float mingap = vals[0] - vals[1];
#pragma unroll
        for (int r = 1; r < TOPK; r++) mingap = fminf(mingap, vals[r] - vals[r + 1]);

        const long long gtok = block_m + tid;
        if (mingap < EPS) {
            int pos = atomicAdd(&g_cnt, 1);
            if (pos < FIX_GRID) g_list[pos] = (int)gtok;
        }

        const float m0f = vals[0];
        float wv[TOPK];
        float s = 0.f;
#pragma unroll
        for (int r = 0; r < TOPK; r++) { wv[r] = __expf(vals[r] - m0f); s += wv[r]; }
        const float inv = 1.f / s;
#pragma unroll
        for (int r = 0; r < TOPK; r++) {
            out[gtok * TOPK + r] = wv[r] * inv;
            out[(long long)T * TOPK + gtok * TOPK + r] = (float)idxs[r];
        }
    }
}

// exact slow path: one block per dense token; all chains in ONE wave.
__global__ __launch_bounds__(64, 4)
void moe_gate_fixup(const float* __restrict__ X, const float* __restrict__ W,
                    float* __restrict__ out, int T) {
    __shared__ float xs[H_DIM];
    __shared__ float lg[N_EXP];
    const int n = g_cnt < FIX_GRID ? g_cnt : FIX_GRID;
    if (blockIdx.x >= n) return;
    const int tok = g_list[blockIdx.x];

    const int e = threadIdx.x;
    {
        const float4* xg = reinterpret_cast<const float4*>(X + (size_t)tok * H_DIM);
        float4* xd = reinterpret_cast<float4*>(xs);
#pragma unroll
        for (int i = 0; i < H_DIM / 4 / 64; i++) xd[e + i * 64] = xg[e + i * 64];
    }
    __syncthreads();

    float acc = 0.f;
    float4 bufA[16], bufB[16];
    const float4* w4 = reinterpret_cast<const float4*>(W + (size_t)e * H_DIM);
#pragma unroll
    for (int j = 0; j < 16; j++) bufA[j] = w4[j];

    for (int c = 0; c < 32; c += 2) {
        if (c + 1 < 32) {
#pragma unroll
            for (int j = 0; j < 16; j++) bufB[j] = w4[(c + 1) * 16 + j];
        }
        const float4* xc = reinterpret_cast<const float4*>(xs + c * 64);
#pragma unroll
        for (int j = 0; j < 16; j++) {       // strict sequential chain
            float4 xv = xc[j];
            acc = fmaf(xv.x, bufA[j].x, acc);
            acc = fmaf(xv.y, bufA[j].y, acc);
            acc = fmaf(xv.z, bufA[j].z, acc);
            acc = fmaf(xv.w, bufA[j].w, acc);
        }
        if (c + 2 < 32) {
#pragma unroll
            for (int j = 0; j < 16; j++) bufA[j] = w4[(c + 2) * 16 + j];
        }
        const float4* xc2 = reinterpret_cast<const float4*>(xs + (c + 1) * 64);
#pragma unroll
        for (int j = 0; j < 16; j++) {
            float4 xv = xc2[j];
            acc = fmaf(xv.x, bufB[j].x, acc);
            acc = fmaf(xv.y, bufB[j].y, acc);
            acc = fmaf(xv.z, bufB[j].z, acc);
            acc = fmaf(xv.w, bufB[j].w, acc);
        }
    }
    lg[e] = acc;
    __syncthreads();

    if (e == 0) {
        float vals[TOPK];
        int   idxs[TOPK];
#pragma unroll
        for (int r = 0; r < TOPK; r++) {
            float best = -__int_as_float(0x7f800000);
            int bi = 0;
            for (int q = 0; q < N_EXP; q++) {
                float v = lg[q];
                if (v > best) { best = v; bi = q; }
            }
            vals[r] = best;
            idxs[r] = bi;
            lg[bi] = -__int_as_float(0x7f800000);
        }
        const float m0f = vals[0];
        float wv[TOPK];
        float sm = 0.f;
#pragma unroll
        for (int r = 0; r < TOPK; r++) { wv[r] = __expf(vals[r] - m0f); sm += wv[r]; }
        const float inv = 1.f / sm;
#pragma unroll
        for (int r = 0; r < TOPK; r++) {
            out[(long long)tok * TOPK + r] = wv[r] * inv;
            out[(long long)T * TOPK + (long long)tok * TOPK + r] = (float)idxs[r];
        }
    }
}

extern "C" void kernel_launch(void* const* d_in, const int* in_sizes, int n_in,
                              void* d_out, int out_size) {
    const float* X = (const float*)d_in[0];   // hidden_states [4,4096,2048] fp32
    const float* W = (const float*)d_in[1];   // weight [64,2048] fp32
    float* out = (float*)d_out;

    const int T = in_sizes[0] / H_DIM;        // 16384
    const int grid = T / BM;                  // 128

    cudaFuncSetAttribute(moe_gate_fast,
                         cudaFuncAttributeMaxDynamicSharedMemorySize, SMEM_BYTES);
    moe_gate_prep<<<(N_EXP * H_DIM) / (256 * 8), 256>>>(W);
    moe_gate_fast<<<grid, NTHREADS, SMEM_BYTES>>>(X, W, out, T);
    moe_gate_fixup<<<FIX_GRID, 64>>>(X, W, out, T);
}